// round 9
// baseline (speedup 1.0000x reference)
#include <cuda_runtime.h>
#include <math.h>

#define NB   32
#define TE   512
#define TM   400
#define NCTA 148
#define NTHR 512

typedef unsigned long long ull;

// ---- persistent smem layout (float indices) ----
#define SM_LOCWP  0                      // 16384 floats = 8192 ull pairs {w[a],w[a+256]}
#define SM_CW     16384                  // 1984 conv w [32f][2][31]
#define SM_LOCB   (16384+1984)           // 512
#define SM_SW     (16384+1984+512)       // 512
#define SM_SCR    (16384+1984+1024)      // 12800 scratch
#define SM_FLOATS (16384+1984+1024+12800)
#define SM_BYTES  (SM_FLOATS*4)

// ---------------- device scratch ----------------
__device__ float  g_keys[(size_t)NB * TE * 512];   // [b][t][a]
__device__ float4 g_w1p[1280 * 512];               // GRU1 packed [k][h]{r,z,n,0}
__device__ float4 g_w2p[1536 * 512];               // GRU2 packed
__device__ float  g_qwT[512 * 512];                // [a][k]
__device__ float  g_decT[128 * 1024];              // [m][k]
__device__ float  g_p1T[256 * 128];                // [p][m]
__device__ float  g_p2T[256 * 256];                // [p][k]
__device__ float  g_haT[2][512 * NB];              // [h][b]
__device__ float  g_hoT[2][512 * NB];
__device__ float  g_ctxT[512 * NB];                // [a][b]
__device__ float  g_decinT[256 * NB];              // [p][b]
__device__ float  g_q[NB * 512];                   // [b][a]
__device__ float  g_attw[NB * TE];
__device__ float  g_attcum[NB * TE];
__device__ float  g_s[NB * TE];
__device__ float  g_lf[(size_t)NB * TE * 32];      // [b][t][f]
__device__ unsigned g_cnt = 0;
__device__ volatile unsigned g_gen = 0;

// ---------------- packed f32x2 helpers ----------------
__device__ __forceinline__ ull dup2(float v) {
    ull r; asm("mov.b64 %0, {%1, %1};" : "=l"(r) : "f"(v)); return r;
}
__device__ __forceinline__ void fma2(ull &d, ull a, ull b) {
    asm("fma.rn.f32x2 %0, %1, %2, %3;" : "=l"(d) : "l"(a), "l"(b), "l"(d));
}
__device__ __forceinline__ float2 unpk(ull v) {
    float2 r; asm("mov.b64 {%0, %1}, %2;" : "=f"(r.x), "=f"(r.y) : "l"(v)); return r;
}
__device__ __forceinline__ ull pk2(float x, float y) {
    ull r; asm("mov.b64 %0, {%1, %2};" : "=l"(r) : "f"(x), "f"(y)); return r;
}

// ---------------- grid barrier ----------------
__device__ __forceinline__ void gsync(unsigned &gen) {
    __syncthreads();
    if (threadIdx.x == 0) {
        __threadfence();
        if (atomicAdd(&g_cnt, 1u) == NCTA - 1) {
            g_cnt = 0;
            __threadfence();
            g_gen = gen + 1;
        } else {
            while (g_gen == gen) { __nanosleep(32); }
        }
        __threadfence();
    }
    __syncthreads();
    gen++;
}

__device__ __forceinline__ float fsig(float v) {
    return __fdividef(1.f, 1.f + __expf(-v));
}
__device__ __forceinline__ float ftanh(float v) {
    float e = __expf(2.f * v);
    return 1.f - __fdividef(2.f, e + 1.f);
}

// ---------------- GRU: CTA(blk<128)=[4b x 32h x 3g]; warps = 2 b-pairs x 8 K-splits ----------------
__device__ __forceinline__ void gru_phase(
    const float4* __restrict__ wp, int L, int Kt,
    const float* __restrict__ bi, const float* __restrict__ bh,
    const float* __restrict__ x0, int l0,
    const float* __restrict__ x1,
    const float* __restrict__ hprev, float* __restrict__ hnew,
    float* sc)
{
    int blk = blockIdx.x;
    if (blk >= 128) { __syncthreads(); __syncthreads(); return; }
    float* sx  = sc;          // Kt*4 <= 6144
    float* red = sc + 6144;   // 512*13 = 6656
    int tid = threadIdx.x, lane = tid & 31, w16 = tid >> 5;
    int b0 = (blk >> 4) * 4;
    int h  = (blk & 15) * 32 + lane;

    // stage x tile [k][4b] (coalesced row reads, 4-lane stores)
    for (int k = w16; k < Kt; k += 16) {
        const float* src = (k < l0) ? (x0 + k * 32)
                         : (k < L)  ? (x1 + (k - l0) * 32)
                                    : (hprev + (k - L) * 32);
        float v = src[lane];
        int d = lane - b0;
        if ((unsigned)d < 4u) sx[k * 4 + d] = v;
    }
    __syncthreads();

    int bg = w16 >> 3, kq = w16 & 7;
    int kb = (kq * Kt) >> 3, ke = ((kq + 1) * Kt) >> 3;
    ull ai0 = 0, ai1 = 0, ai2 = 0, ah0 = 0, ah1 = 0, ah2 = 0;

    const float4* wph = wp + h;
    int s1e = ke < L ? ke : L;
#pragma unroll 4
    for (int k = kb; k < s1e; k++) {
        float4 wv = __ldg(wph + (size_t)k * 512);
        ull xp = *(const ull*)(sx + k * 4 + bg * 2);
        fma2(ai0, xp, dup2(wv.x));
        fma2(ai1, xp, dup2(wv.y));
        fma2(ai2, xp, dup2(wv.z));
    }
    int s2b = kb > L ? kb : L;
#pragma unroll 4
    for (int k = s2b; k < ke; k++) {
        float4 wv = __ldg(wph + (size_t)k * 512);
        ull xp = *(const ull*)(sx + k * 4 + bg * 2);
        fma2(ah0, xp, dup2(wv.x));
        fma2(ah1, xp, dup2(wv.y));
        fma2(ah2, xp, dup2(wv.z));
    }
    {
        float* r = red + tid * 13;
        float2 t;
        t = unpk(ai0); r[0] = t.x; r[6]  = t.y;
        t = unpk(ai1); r[1] = t.x; r[7]  = t.y;
        t = unpk(ai2); r[2] = t.x; r[8]  = t.y;
        t = unpk(ah0); r[3] = t.x; r[9]  = t.y;
        t = unpk(ah1); r[4] = t.x; r[10] = t.y;
        t = unpk(ah2); r[5] = t.x; r[11] = t.y;
    }
    __syncthreads();

    if (tid < 128) {
        int bj = tid >> 5;
        int b = b0 + bj;
        int hh = (blk & 15) * 32 + lane;
        int bgr = bj >> 1, jr = bj & 1;
        float gs[6] = {0.f, 0.f, 0.f, 0.f, 0.f, 0.f};
#pragma unroll
        for (int k2 = 0; k2 < 8; k2++) {
            const float* r = red + ((bgr * 8 + k2) * 32 + lane) * 13 + jr * 6;
#pragma unroll
            for (int g = 0; g < 6; g++) gs[g] += r[g];
        }
        float r = fsig(gs[0] + __ldg(bi + hh) + gs[3] + __ldg(bh + hh));
        float z = fsig(gs[1] + __ldg(bi + 512 + hh) + gs[4] + __ldg(bh + 512 + hh));
        float n = ftanh(gs[2] + __ldg(bi + 1024 + hh) + r * (gs[5] + __ldg(bh + 1024 + hh)));
        float hp = hprev[hh * 32 + b];
        hnew[hh * 32 + b] = (1.f - z) * n + z * hp;
    }
    __syncthreads();
}

// ---------------- the single persistent kernel ----------------
__global__ void __launch_bounds__(NTHR, 1) decoder_kernel(
    const float* __restrict__ enc, const int* __restrict__ tlens, const int* __restrict__ mlens,
    const float* __restrict__ pre_w1, const float* __restrict__ pre_w2,
    const float* __restrict__ attn_wi, const float* __restrict__ attn_wh,
    const float* __restrict__ attn_bi, const float* __restrict__ attn_bh,
    const float* __restrict__ q_w, const float* __restrict__ k_w,
    const float* __restrict__ score_w, const float* __restrict__ score_b,
    const float* __restrict__ loc_cw, const float* __restrict__ loc_w, const float* __restrict__ loc_b,
    const float* __restrict__ out_wi, const float* __restrict__ out_wh,
    const float* __restrict__ out_bi, const float* __restrict__ out_bh,
    const float* __restrict__ dec_w, const float* __restrict__ dec_b,
    const float* __restrict__ gate_w, const float* __restrict__ gate_b,
    float* __restrict__ out_mel, float* __restrict__ out_gate,
    float* __restrict__ out_attn, float* __restrict__ out_mask)
{
    extern __shared__ float sm[];
    ull*   locwp  = (ull*)(sm + SM_LOCWP);   // 8192 pairs
    float* cw_s   = sm + SM_CW;
    float* locb_s = sm + SM_LOCB;
    float* sw_s   = sm + SM_SW;
    float* sc     = sm + SM_SCR;

    int blk = blockIdx.x, tid = threadIdx.x, lane = tid & 31, w16 = tid >> 5;
    int gid = blk * NTHR + tid, gstride = NCTA * NTHR;
    unsigned gen = g_gen;

    // persistent smem weights
    for (int v = tid; v < 8192; v += NTHR) {
        int f = v >> 8, ap = v & 255;
        locwp[v] = pk2(loc_w[f * 512 + ap], loc_w[f * 512 + ap + 256]);
    }
    for (int v = tid; v < 1984; v += NTHR) cw_s[v] = loc_cw[v];
    for (int v = tid; v < 512; v += NTHR) { locb_s[v] = loc_b[v]; sw_s[v] = score_w[v]; }

    // state init
    for (int v = gid; v < 512 * NB; v += gstride) {
        g_haT[0][v] = 0.f; g_hoT[0][v] = 0.f; g_ctxT[v] = 0.f;
    }
    for (int v = gid; v < 256 * NB; v += gstride) g_decinT[v] = 0.f;
    for (int v = gid; v < NB * TE; v += gstride) { g_attw[v] = 0.f; g_attcum[v] = 0.f; }

    // weight packs / transposes
    for (int idx = gid; idx < 1280 * 512; idx += gstride) {
        int k = idx >> 9, h = idx & 511;
        const float* src = (k < 768) ? (attn_wi + (size_t)k * 1536)
                                     : (attn_wh + (size_t)(k - 768) * 1536);
        g_w1p[idx] = make_float4(src[h], src[h + 512], src[h + 1024], 0.f);
    }
    for (int idx = gid; idx < 1536 * 512; idx += gstride) {
        int k = idx >> 9, h = idx & 511;
        const float* src = (k < 1024) ? (out_wi + (size_t)k * 1536)
                                      : (out_wh + (size_t)(k - 1024) * 1536);
        g_w2p[idx] = make_float4(src[h], src[h + 512], src[h + 1024], 0.f);
    }
    for (int idx = gid; idx < 512 * 512; idx += gstride) {
        int a = idx >> 9, k = idx & 511;
        g_qwT[idx] = q_w[(size_t)k * 512 + a];
    }
    for (int idx = gid; idx < 128 * 1024; idx += gstride) {
        int m = idx >> 10, k = idx & 1023;
        g_decT[idx] = dec_w[(size_t)k * 128 + m];
    }
    for (int idx = gid; idx < 256 * 128; idx += gstride) {
        int p = idx >> 7, m = idx & 127;
        g_p1T[idx] = pre_w1[m * 256 + p];
    }
    for (int idx = gid; idx < 256 * 256; idx += gstride) {
        int p = idx >> 8, k = idx & 255;
        g_p2T[idx] = pre_w2[k * 256 + p];
    }

    // ---- keys_p = enc @ k_w ----
    {
        int a = w16 * 32 + lane;
        for (int job = blk; job < 512; job += NCTA) {
            int b = job >> 4, tc2 = (job & 15) * 32;
            float a0[32];
#pragma unroll
            for (int t = 0; t < 32; t++) a0[t] = 0.f;
            for (int k0 = 0; k0 < 1024; k0 += 32) {
                __syncthreads();
                for (int v = tid; v < 1024; v += NTHR)
                    sc[v] = enc[(size_t)(b * TE + tc2 + (v >> 5)) * 1024 + k0 + (v & 31)];
                __syncthreads();
#pragma unroll
                for (int k4 = 0; k4 < 8; k4++) {
                    const float* kwp = k_w + (size_t)(k0 + k4 * 4) * 512 + a;
                    float w0 = __ldg(kwp), w1 = __ldg(kwp + 512), w2 = __ldg(kwp + 1024), w3 = __ldg(kwp + 1536);
#pragma unroll
                    for (int t = 0; t < 32; t++) {
                        float4 e = *(const float4*)(sc + t * 32 + k4 * 4);
                        a0[t] = fmaf(e.x, w0, fmaf(e.y, w1, fmaf(e.z, w2, fmaf(e.w, w3, a0[t]))));
                    }
                }
            }
#pragma unroll
            for (int t = 0; t < 32; t++)
                g_keys[(size_t)(b * TE + tc2 + t) * 512 + a] = a0[t];
        }
    }
    gsync(gen);

    for (int step = 0; step < TM; step++) {
        int prev = step & 1, cur = prev ^ 1;
        float* haP = g_haT[prev]; float* haC = g_haT[cur];
        float* hoP = g_hoT[prev]; float* hoC = g_hoT[cur];

        // ---- P1: attention GRU ----
        gru_phase(g_w1p, 768, 1280, attn_bi, attn_bh,
                  g_decinT, 256, g_ctxT, haP, haC, sc);
        gsync(gen);

        // ---- P2: conv (blk<128) || q projection (blk 128..147) ----
        if (blk < 128) {
            int b = blk >> 2, tc2 = (blk & 3) * 128;
            int len = tlens[b];
            if (tc2 <= len) {
                float* sa  = sc;
                float* sb2 = sc + 160;
                for (int i = tid; i < 158; i += NTHR) {
                    int tt = tc2 + i - 15;
                    bool ok = (unsigned)tt < 512u;
                    sa[i]  = ok ? g_attw[b * 512 + tt]   : 0.f;
                    sb2[i] = ok ? g_attcum[b * 512 + tt] : 0.f;
                }
                __syncthreads();
                // f = lane, 8 t per thread via broadcast LDS
                int tb = w16 * 8;
                float acc[8];
#pragma unroll
                for (int j = 0; j < 8; j++) acc[j] = 0.f;
#pragma unroll 4
                for (int kk = 0; kk < 31; kk++) {
                    float w0 = cw_s[lane * 62 + kk];
                    float w1 = cw_s[lane * 62 + 31 + kk];
#pragma unroll
                    for (int j = 0; j < 8; j++)
                        acc[j] = fmaf(sa[tb + kk + j], w0, fmaf(sb2[tb + kk + j], w1, acc[j]));
                }
#pragma unroll
                for (int j = 0; j < 8; j++)
                    g_lf[(size_t)(b * 512 + tc2 + tb + j) * 32 + lane] = acc[j];
            }
        } else {
            float* xh = sc;
            for (int job = blk - 128; job < NB; job += 20) {
                int b = job;
                __syncthreads();
                for (int i = tid; i < 512; i += NTHR) xh[i] = haC[i * 32 + b];
                __syncthreads();
#pragma unroll 2
                for (int r = 0; r < 32; r++) {
                    int a = w16 * 32 + r;
                    const float4* qw4 = (const float4*)(g_qwT + (size_t)a * 512) + lane;
                    float acc = 0.f;
#pragma unroll
                    for (int c = 0; c < 4; c++) {
                        float4 wv = __ldg(qw4 + c * 32);
                        float4 xv = *(const float4*)(xh + (c * 32 + lane) * 4);
                        acc = fmaf(wv.x, xv.x, fmaf(wv.y, xv.y, fmaf(wv.z, xv.z, fmaf(wv.w, xv.w, acc))));
                    }
#pragma unroll
                    for (int o = 16; o; o >>= 1) acc += __shfl_xor_sync(0xffffffffu, acc, o);
                    if (lane == 0) g_q[(b << 9) + a] = acc;
                }
            }
        }
        gsync(gen);

        // ---- P3: score (packed f32x2 over a-pairs) ----
        for (int job = blk; job < 256; job += NCTA) {
            int bb = job >> 3;
            int len = tlens[bb];
            int tmin = (job & 7) * 64;
            if (tmin > len) continue;
            int t0 = tmin + w16 * 4;

            float lfv[4];
#pragma unroll
            for (int j = 0; j < 4; j++)
                lfv[j] = g_lf[(size_t)((bb << 9) + t0 + j) * 32 + lane];

            ull acc[4][8];
#pragma unroll
            for (int j = 0; j < 4; j++)
#pragma unroll
                for (int i = 0; i < 8; i++) acc[j][i] = 0;

#pragma unroll 2
            for (int f = 0; f < 32; f++) {
                ull d0 = dup2(__shfl_sync(0xffffffffu, lfv[0], f));
                ull d1 = dup2(__shfl_sync(0xffffffffu, lfv[1], f));
                ull d2 = dup2(__shfl_sync(0xffffffffu, lfv[2], f));
                ull d3 = dup2(__shfl_sync(0xffffffffu, lfv[3], f));
                const ull* lw = locwp + f * 256 + lane;
#pragma unroll
                for (int i = 0; i < 8; i++) {
                    ull w2 = lw[32 * i];
                    fma2(acc[0][i], d0, w2);
                    fma2(acc[1][i], d1, w2);
                    fma2(acc[2][i], d2, w2);
                    fma2(acc[3][i], d3, w2);
                }
            }
            float sbv = __ldg(score_b);
            const float* qb = g_q + (bb << 9);
#pragma unroll
            for (int j = 0; j < 4; j++) {
                int t = t0 + j;
                if (t > len) continue;
                float p = 0.f;
                const float* kp = g_keys + (size_t)((bb << 9) + t) * 512;
#pragma unroll
                for (int i = 0; i < 8; i++) {
                    float2 av = unpk(acc[j][i]);
                    int a = lane + 32 * i;
                    float v1 = av.x + __ldg(qb + a)       + locb_s[a]       + kp[a];
                    float v2 = av.y + __ldg(qb + a + 256) + locb_s[a + 256] + kp[a + 256];
                    p = fmaf(ftanh(v1), sw_s[a], p);
                    p = fmaf(ftanh(v2), sw_s[a + 256], p);
                }
#pragma unroll
                for (int o = 16; o; o >>= 1) p += __shfl_xor_sync(0xffffffffu, p, o);
                if (lane == 0) g_s[(bb << 9) + t] = p + sbv;
            }
        }
        gsync(gen);

        // ---- P4: softmax + attcum + context (blk<32) ----
        if (blk < NB) {
            int b = blk;
            int len = tlens[b];
            float* shw  = sc;          // 512
            float* ctmp = sc + 512;    // 2048
            float* redm = sc + 2560;   // 18
            bool valid = (tid <= len);
            float sv = valid ? g_s[(b << 9) + tid] : -1e30f;

            float m = sv;
#pragma unroll
            for (int o = 16; o; o >>= 1) m = fmaxf(m, __shfl_xor_sync(0xffffffffu, m, o));
            if (lane == 0) redm[w16] = m;
            __syncthreads();
            if (tid == 0) {
                float mm = redm[0];
#pragma unroll
                for (int i = 1; i < 16; i++) mm = fmaxf(mm, redm[i]);
                redm[16] = mm;
            }
            __syncthreads();
            float mx = redm[16];
            float e = valid ? __expf(sv - mx) : 0.f;
            float ss = e;
#pragma unroll
            for (int o = 16; o; o >>= 1) ss += __shfl_xor_sync(0xffffffffu, ss, o);
            __syncthreads();
            if (lane == 0) redm[w16] = ss;
            __syncthreads();
            if (tid == 0) {
                float t = 0.f;
#pragma unroll
                for (int i = 0; i < 16; i++) t += redm[i];
                redm[17] = __fdividef(1.f, t);
            }
            __syncthreads();
            float w = e * redm[17];

            g_attw[(b << 9) + tid] = w;
            g_attcum[(b << 9) + tid] += w;
            out_attn[(size_t)(b * TM + step) * 512 + tid] = w;
            shw[tid] = w;
            __syncthreads();

            // context: 4-way t-split, float4 over a
            int tq = tid >> 7, a4 = (tid & 127) * 4;
            float4 c4 = make_float4(0.f, 0.f, 0.f, 0.f);
            for (int t = tq; t <= len; t += 4) {
                float wv = shw[t];
                float4 kv = *(const float4*)(g_keys + ((size_t)(b << 9) + t) * 512 + a4);
                c4.x = fmaf(wv, kv.x, c4.x);
                c4.y = fmaf(wv, kv.y, c4.y);
                c4.z = fmaf(wv, kv.z, c4.z);
                c4.w = fmaf(wv, kv.w, c4.w);
            }
            *(float4*)(ctmp + tq * 512 + a4) = c4;
            __syncthreads();
            float c = ctmp[tid] + ctmp[512 + tid] + ctmp[1024 + tid] + ctmp[1536 + tid];
            g_ctxT[tid * 32 + b] = c;
        }
        gsync(gen);

        // ---- P5: output GRU ----
        gru_phase(g_w2p, 1024, 1536, out_bi, out_bh,
                  haC, 512, g_ctxT, hoP, hoC, sc);
        gsync(gen);

        // ---- P6: mel / gate / prenet (blk<32) ----
        if (blk < NB) {
            int b = blk;
            float* xh   = sc;          // 1024
            float* melS = sc + 1024;   // 128
            float* p1S  = sc + 1152;   // 256
            float* gred = sc + 1408;   // 16
            for (int i = tid; i < 512; i += NTHR) {
                xh[i]       = hoC[i * 32 + b];
                xh[512 + i] = g_ctxT[i * 32 + b];
            }
            __syncthreads();

            // dec GEMM: warp per m-row (16 warps x 8 rows)
#pragma unroll
            for (int r = 0; r < 8; r++) {
                int mm = w16 * 8 + r;
                const float4* dw = (const float4*)(g_decT + (size_t)mm * 1024) + lane;
                float acc = 0.f;
#pragma unroll
                for (int c = 0; c < 8; c++) {
                    float4 wv = __ldg(dw + c * 32);
                    float4 xv = *(const float4*)(xh + (c * 32 + lane) * 4);
                    acc = fmaf(wv.x, xv.x, fmaf(wv.y, xv.y, fmaf(wv.z, xv.z, fmaf(wv.w, xv.w, acc))));
                }
#pragma unroll
                for (int o = 16; o; o >>= 1) acc += __shfl_xor_sync(0xffffffffu, acc, o);
                if (lane == 0) melS[mm] = acc + __ldg(dec_b + mm);
            }
            // gate partials
            {
                float gp = xh[tid] * __ldg(gate_w + tid) + xh[512 + tid] * __ldg(gate_w + 512 + tid);
#pragma unroll
                for (int o = 16; o; o >>= 1) gp += __shfl_xor_sync(0xffffffffu, gp, o);
                if (lane == 0) gred[w16] = gp;
            }
            __syncthreads();

            int mask = step > mlens[b];
            if (tid < 128)
                out_mel[(size_t)(b * TM + step) * 128 + tid] = mask ? 0.f : melS[tid];
            if (tid == 0) {
                float g = __ldg(gate_b);
#pragma unroll
                for (int i = 0; i < 16; i++) g += gred[i];
                out_gate[b * TM + step] = mask ? 1000.f : g;
                out_mask[b * TM + step] = mask ? 1.f : 0.f;
            }
            __syncthreads();

            // prenet1: warp per p-row (16 warps x 16 rows)
#pragma unroll
            for (int r = 0; r < 16; r++) {
                int p = w16 * 16 + r;
                float4 wv = __ldg((const float4*)(g_p1T + p * 128) + lane);
                float4 xv = *(const float4*)(melS + lane * 4);
                float acc = fmaf(wv.x, xv.x, fmaf(wv.y, xv.y, fmaf(wv.z, xv.z, wv.w * xv.w)));
#pragma unroll
                for (int o = 16; o; o >>= 1) acc += __shfl_xor_sync(0xffffffffu, acc, o);
                if (lane == 0) p1S[p] = fmaxf(acc, 0.f);
            }
            __syncthreads();

            // prenet2: warp per p-row
#pragma unroll
            for (int r = 0; r < 16; r++) {
                int p = w16 * 16 + r;
                const float4* w4 = (const float4*)(g_p2T + p * 256) + lane;
                float acc = 0.f;
#pragma unroll
                for (int c = 0; c < 2; c++) {
                    float4 wv = __ldg(w4 + c * 32);
                    float4 xv = *(const float4*)(p1S + (c * 32 + lane) * 4);
                    acc = fmaf(wv.x, xv.x, fmaf(wv.y, xv.y, fmaf(wv.z, xv.z, fmaf(wv.w, xv.w, acc))));
                }
#pragma unroll
                for (int o = 16; o; o >>= 1) acc += __shfl_xor_sync(0xffffffffu, acc, o);
                if (lane == 0) g_decinT[p * 32 + b] = fmaxf(acc, 0.f);
            }
        }
        gsync(gen);
    }
}

// ---------------- host ----------------
extern "C" void kernel_launch(void* const* d_in, const int* in_sizes, int n_in,
                              void* d_out, int out_size) {
    int off = n_in - 26;
    auto W = [&](int i) -> const float* {
        return (const float*)d_in[i >= 5 ? i + off : i];
    };
    const float* enc = (const float*)d_in[0];
    const int* tlens = (const int*)d_in[2];
    const int* mlens = (const int*)d_in[3];
    const float* pre_w1 = W(5), *pre_w2 = W(6);
    const float* attn_wi = W(7), *attn_wh = W(8), *attn_bi = W(9), *attn_bh = W(10);
    const float* q_w = W(11), *k_w = W(12);
    const float* score_w = W(13), *score_b = W(14);
    const float* loc_cw = W(15), *loc_w = W(16), *loc_b = W(17);
    const float* out_wi = W(18), *out_wh = W(19), *out_bi = W(20), *out_bh = W(21);
    const float* dec_w = W(22), *dec_b = W(23);
    const float* gate_w = W(24), *gate_b = W(25);

    float* out = (float*)d_out;
    float* out_mel  = out;
    float* out_gate = out + (size_t)NB * TM * 128;
    float* out_attn = out_gate + (size_t)NB * TM;
    float* out_mask = out_attn + (size_t)NB * TM * 512;

    static int configured = 0;
    if (!configured) {
        cudaFuncSetAttribute(decoder_kernel,
                             cudaFuncAttributeMaxDynamicSharedMemorySize, SM_BYTES);
        configured = 1;
    }

    decoder_kernel<<<NCTA, NTHR, SM_BYTES>>>(
        enc, tlens, mlens, pre_w1, pre_w2,
        attn_wi, attn_wh, attn_bi, attn_bh,
        q_w, k_w, score_w, score_b,
        loc_cw, loc_w, loc_b,
        out_wi, out_wh, out_bi, out_bh,
        dec_w, dec_b, gate_w, gate_b,
        out_mel, out_gate, out_attn, out_mask);
}

// round 10
// speedup vs baseline: 1.1575x; 1.1575x over previous
#include <cuda_runtime.h>
#include <math.h>

#define NB   32
#define TE   512
#define TM   400
#define NCTA 148
#define NTHR 512

typedef unsigned long long ull;

#define SM_LOCWP  0
#define SM_CW     16384
#define SM_LOCB   (16384+1984)
#define SM_SW     (16384+1984+512)
#define SM_SCR    (16384+1984+1024)
#define SM_FLOATS (16384+1984+1024+12800)
#define SM_BYTES  (SM_FLOATS*4)

__device__ float  g_keys[(size_t)NB * TE * 512];
__device__ float4 g_w1p[1280 * 512];
__device__ float4 g_w2p[1536 * 512];
__device__ float  g_qwT[512 * 512];
__device__ float  g_decT[128 * 1024];
__device__ float  g_p1T[256 * 128];
__device__ float  g_p2T[256 * 256];
__device__ float  g_haT[2][512 * NB];
__device__ float  g_hoT[2][512 * NB];
__device__ float  g_haR[NB * 512];
__device__ float  g_hoR[NB * 512];
__device__ float  g_ctxR[NB * 512];
__device__ float  g_ctxT[512 * NB];
__device__ float  g_decinT[256 * NB];
__device__ float  g_q[NB * 512];
__device__ float  g_attw[NB * TE];
__device__ float  g_attcum[NB * TE];
__device__ float  g_s[NB * TE];
__device__ float  g_lf[(size_t)NB * TE * 32];
__device__ int    g_jc[TM];
__device__ unsigned g_cnt = 0;
__device__ volatile unsigned g_gen = 0;

__device__ __forceinline__ ull dup2(float v) {
    ull r; asm("mov.b64 %0, {%1, %1};" : "=l"(r) : "f"(v)); return r;
}
__device__ __forceinline__ void fma2(ull &d, ull a, ull b) {
    asm("fma.rn.f32x2 %0, %1, %2, %3;" : "=l"(d) : "l"(a), "l"(b), "l"(d));
}
__device__ __forceinline__ float2 unpk(ull v) {
    float2 r; asm("mov.b64 {%0, %1}, %2;" : "=f"(r.x), "=f"(r.y) : "l"(v)); return r;
}
__device__ __forceinline__ ull pk2(float x, float y) {
    ull r; asm("mov.b64 %0, {%1, %2};" : "=l"(r) : "f"(x), "f"(y)); return r;
}

__device__ __forceinline__ void gsync(unsigned &gen) {
    __syncthreads();
    if (threadIdx.x == 0) {
        __threadfence();
        if (atomicAdd(&g_cnt, 1u) == NCTA - 1) {
            g_cnt = 0;
            __threadfence();
            g_gen = gen + 1;
        } else {
            while (g_gen == gen) { __nanosleep(32); }
        }
        __threadfence();
    }
    __syncthreads();
    gen++;
}

__device__ __forceinline__ float fsig(float v) {
    return __fdividef(1.f, 1.f + __expf(-v));
}
__device__ __forceinline__ float ftanh(float v) {
    float e = __expf(2.f * v);
    return 1.f - __fdividef(2.f, e + 1.f);
}

// GRU: CTA(blk<128)=[4b x 32h]; warps = 2 b-pairs x 8 K-splits
__device__ __forceinline__ void gru_phase(
    const float4* __restrict__ wp, int L, int Kt,
    const float* __restrict__ bi, const float* __restrict__ bh,
    const float* __restrict__ x0, int l0,
    const float* __restrict__ x1,
    const float* __restrict__ hprev, float* __restrict__ hnew,
    float* __restrict__ hnewR, float* sc)
{
    int blk = blockIdx.x;
    if (blk >= 128) { __syncthreads(); __syncthreads(); return; }
    float* sx  = sc;
    float* red = sc + 6144;
    int tid = threadIdx.x, lane = tid & 31, w16 = tid >> 5;
    int b0 = (blk >> 4) * 4;
    int h  = (blk & 15) * 32 + lane;

    for (int k = w16; k < Kt; k += 16) {
        const float* src = (k < l0) ? (x0 + k * 32)
                         : (k < L)  ? (x1 + (k - l0) * 32)
                                    : (hprev + (k - L) * 32);
        float v = src[lane];
        int d = lane - b0;
        if ((unsigned)d < 4u) sx[k * 4 + d] = v;
    }
    __syncthreads();

    int bg = w16 >> 3, kq = w16 & 7;
    int kb = (kq * Kt) >> 3, ke = ((kq + 1) * Kt) >> 3;
    ull ai0 = 0, ai1 = 0, ai2 = 0, ah0 = 0, ah1 = 0, ah2 = 0;

    const float4* wph = wp + h;
    int s1e = ke < L ? ke : L;
#pragma unroll 4
    for (int k = kb; k < s1e; k++) {
        float4 wv = __ldg(wph + (size_t)k * 512);
        ull xp = *(const ull*)(sx + k * 4 + bg * 2);
        fma2(ai0, xp, dup2(wv.x));
        fma2(ai1, xp, dup2(wv.y));
        fma2(ai2, xp, dup2(wv.z));
    }
    int s2b = kb > L ? kb : L;
#pragma unroll 4
    for (int k = s2b; k < ke; k++) {
        float4 wv = __ldg(wph + (size_t)k * 512);
        ull xp = *(const ull*)(sx + k * 4 + bg * 2);
        fma2(ah0, xp, dup2(wv.x));
        fma2(ah1, xp, dup2(wv.y));
        fma2(ah2, xp, dup2(wv.z));
    }
    {
        float* r = red + tid * 13;
        float2 t;
        t = unpk(ai0); r[0] = t.x; r[6]  = t.y;
        t = unpk(ai1); r[1] = t.x; r[7]  = t.y;
        t = unpk(ai2); r[2] = t.x; r[8]  = t.y;
        t = unpk(ah0); r[3] = t.x; r[9]  = t.y;
        t = unpk(ah1); r[4] = t.x; r[10] = t.y;
        t = unpk(ah2); r[5] = t.x; r[11] = t.y;
    }
    __syncthreads();

    if (tid < 128) {
        int bj = tid >> 5;
        int b = b0 + bj;
        int hh = (blk & 15) * 32 + lane;
        int bgr = bj >> 1, jr = bj & 1;
        float gs[6] = {0.f, 0.f, 0.f, 0.f, 0.f, 0.f};
#pragma unroll
        for (int k2 = 0; k2 < 8; k2++) {
            const float* r = red + ((bgr * 8 + k2) * 32 + lane) * 13 + jr * 6;
#pragma unroll
            for (int g = 0; g < 6; g++) gs[g] += r[g];
        }
        float r = fsig(gs[0] + __ldg(bi + hh) + gs[3] + __ldg(bh + hh));
        float z = fsig(gs[1] + __ldg(bi + 512 + hh) + gs[4] + __ldg(bh + 512 + hh));
        float n = ftanh(gs[2] + __ldg(bi + 1024 + hh) + r * (gs[5] + __ldg(bh + 1024 + hh)));
        float hp = hprev[hh * 32 + b];
        float val = (1.f - z) * n + z * hp;
        hnew[hh * 32 + b] = val;
        hnewR[b * 512 + hh] = val;
    }
    __syncthreads();
}

__global__ void __launch_bounds__(NTHR, 1) decoder_kernel(
    const float* __restrict__ enc, const int* __restrict__ tlens, const int* __restrict__ mlens,
    const float* __restrict__ pre_w1, const float* __restrict__ pre_w2,
    const float* __restrict__ attn_wi, const float* __restrict__ attn_wh,
    const float* __restrict__ attn_bi, const float* __restrict__ attn_bh,
    const float* __restrict__ q_w, const float* __restrict__ k_w,
    const float* __restrict__ score_w, const float* __restrict__ score_b,
    const float* __restrict__ loc_cw, const float* __restrict__ loc_w, const float* __restrict__ loc_b,
    const float* __restrict__ out_wi, const float* __restrict__ out_wh,
    const float* __restrict__ out_bi, const float* __restrict__ out_bh,
    const float* __restrict__ dec_w, const float* __restrict__ dec_b,
    const float* __restrict__ gate_w, const float* __restrict__ gate_b,
    float* __restrict__ out_mel, float* __restrict__ out_gate,
    float* __restrict__ out_attn, float* __restrict__ out_mask)
{
    extern __shared__ float sm[];
    ull*   locwp  = (ull*)(sm + SM_LOCWP);
    float* cw_s   = sm + SM_CW;
    float* locb_s = sm + SM_LOCB;
    float* sw_s   = sm + SM_SW;
    float* sc     = sm + SM_SCR;
    __shared__ int sjob;

    int blk = blockIdx.x, tid = threadIdx.x, lane = tid & 31, w16 = tid >> 5;
    int gid = blk * NTHR + tid, gstride = NCTA * NTHR;
    unsigned gen = g_gen;

    for (int v = tid; v < 8192; v += NTHR) {
        int f = v >> 8, ap = v & 255;
        locwp[v] = pk2(loc_w[f * 512 + ap], loc_w[f * 512 + ap + 256]);
    }
    for (int v = tid; v < 1984; v += NTHR) cw_s[v] = loc_cw[v];
    for (int v = tid; v < 512; v += NTHR) { locb_s[v] = loc_b[v]; sw_s[v] = score_w[v]; }

    for (int v = gid; v < 512 * NB; v += gstride) {
        g_haT[0][v] = 0.f; g_hoT[0][v] = 0.f; g_ctxT[v] = 0.f; g_haR[v] = 0.f;
    }
    for (int v = gid; v < 256 * NB; v += gstride) g_decinT[v] = 0.f;
    for (int v = gid; v < NB * TE; v += gstride) { g_attw[v] = 0.f; g_attcum[v] = 0.f; }
    for (int v = gid; v < TM; v += gstride) g_jc[v] = 0;

    for (int idx = gid; idx < 1280 * 512; idx += gstride) {
        int k = idx >> 9, h = idx & 511;
        const float* src = (k < 768) ? (attn_wi + (size_t)k * 1536)
                                     : (attn_wh + (size_t)(k - 768) * 1536);
        g_w1p[idx] = make_float4(src[h], src[h + 512], src[h + 1024], 0.f);
    }
    for (int idx = gid; idx < 1536 * 512; idx += gstride) {
        int k = idx >> 9, h = idx & 511;
        const float* src = (k < 1024) ? (out_wi + (size_t)k * 1536)
                                      : (out_wh + (size_t)(k - 1024) * 1536);
        g_w2p[idx] = make_float4(src[h], src[h + 512], src[h + 1024], 0.f);
    }
    for (int idx = gid; idx < 512 * 512; idx += gstride) {
        int a = idx >> 9, k = idx & 511;
        g_qwT[idx] = q_w[(size_t)k * 512 + a];
    }
    for (int idx = gid; idx < 128 * 1024; idx += gstride) {
        int m = idx >> 10, k = idx & 1023;
        g_decT[idx] = dec_w[(size_t)k * 128 + m];
    }
    for (int idx = gid; idx < 256 * 128; idx += gstride) {
        int p = idx >> 7, m = idx & 127;
        g_p1T[idx] = pre_w1[m * 256 + p];
    }
    for (int idx = gid; idx < 256 * 256; idx += gstride) {
        int p = idx >> 8, k = idx & 255;
        g_p2T[idx] = pre_w2[k * 256 + p];
    }

    // keys_p = enc @ k_w
    {
        int a = w16 * 32 + lane;
        for (int job = blk; job < 512; job += NCTA) {
            int b = job >> 4, tc2 = (job & 15) * 32;
            float a0[32];
#pragma unroll
            for (int t = 0; t < 32; t++) a0[t] = 0.f;
            for (int k0 = 0; k0 < 1024; k0 += 32) {
                __syncthreads();
                for (int v = tid; v < 1024; v += NTHR)
                    sc[v] = enc[(size_t)(b * TE + tc2 + (v >> 5)) * 1024 + k0 + (v & 31)];
                __syncthreads();
#pragma unroll
                for (int k4 = 0; k4 < 8; k4++) {
                    const float* kwp = k_w + (size_t)(k0 + k4 * 4) * 512 + a;
                    float w0 = __ldg(kwp), w1 = __ldg(kwp + 512), w2 = __ldg(kwp + 1024), w3 = __ldg(kwp + 1536);
#pragma unroll
                    for (int t = 0; t < 32; t++) {
                        float4 e = *(const float4*)(sc + t * 32 + k4 * 4);
                        a0[t] = fmaf(e.x, w0, fmaf(e.y, w1, fmaf(e.z, w2, fmaf(e.w, w3, a0[t]))));
                    }
                }
            }
#pragma unroll
            for (int t = 0; t < 32; t++)
                g_keys[(size_t)(b * TE + tc2 + t) * 512 + a] = a0[t];
        }
    }
    gsync(gen);

    for (int step = 0; step < TM; step++) {
        int prev = step & 1, cur = prev ^ 1;
        float* haP = g_haT[prev]; float* haC = g_haT[cur];
        float* hoP = g_hoT[prev]; float* hoC = g_hoT[cur];

        // P1: attention GRU (writes haC + haR)
        gru_phase(g_w1p, 768, 1280, attn_bi, attn_bh,
                  g_decinT, 256, g_ctxT, haP, haC, g_haR, sc);
        gsync(gen);

        // P2: conv (blk<128) then q on ALL CTAs (512 jobs, reads haR coalesced)
        if (blk < 128) {
            int b = blk >> 2, tc2 = (blk & 3) * 128;
            int len = tlens[b];
            if (tc2 <= len) {
                float* sa  = sc;
                float* sb2 = sc + 160;
                for (int i = tid; i < 158; i += NTHR) {
                    int tt = tc2 + i - 15;
                    bool ok = (unsigned)tt < 512u;
                    sa[i]  = ok ? g_attw[b * 512 + tt]   : 0.f;
                    sb2[i] = ok ? g_attcum[b * 512 + tt] : 0.f;
                }
                __syncthreads();
                int tb = w16 * 8;
                float acc[8];
#pragma unroll
                for (int j = 0; j < 8; j++) acc[j] = 0.f;
#pragma unroll 4
                for (int kk = 0; kk < 31; kk++) {
                    float w0 = cw_s[lane * 62 + kk];
                    float w1 = cw_s[lane * 62 + 31 + kk];
#pragma unroll
                    for (int j = 0; j < 8; j++)
                        acc[j] = fmaf(sa[tb + kk + j], w0, fmaf(sb2[tb + kk + j], w1, acc[j]));
                }
#pragma unroll
                for (int j = 0; j < 8; j++)
                    g_lf[(size_t)(b * 512 + tc2 + tb + j) * 32 + lane] = acc[j];
            }
            __syncthreads();
        }
        for (int j = blk; j < 512; j += NCTA) {
            int b = j >> 4;
            const float* xr = g_haR + (b << 9);
#pragma unroll
            for (int rr = 0; rr < 2; rr++) {
                int a = (j & 15) * 32 + w16 * 2 + rr;
                const float4* qw4 = (const float4*)(g_qwT + (size_t)a * 512) + lane;
                const float4* xv4 = (const float4*)xr + lane;
                float acc = 0.f;
#pragma unroll
                for (int c = 0; c < 4; c++) {
                    float4 wv = __ldg(qw4 + c * 32);
                    float4 xv = __ldg(xv4 + c * 32);
                    acc = fmaf(wv.x, xv.x, fmaf(wv.y, xv.y, fmaf(wv.z, xv.z, fmaf(wv.w, xv.w, acc))));
                }
#pragma unroll
                for (int o = 16; o; o >>= 1) acc += __shfl_xor_sync(0xffffffffu, acc, o);
                if (lane == 0) g_q[(b << 9) + a] = acc;
            }
        }
        gsync(gen);

        // P3: score via work queue (256 jobs of 64t)
        {
            float sbv = __ldg(score_b);
            for (;;) {
                __syncthreads();
                if (tid == 0) sjob = atomicAdd(&g_jc[step], 1);
                __syncthreads();
                int job = sjob;
                if (job >= 256) break;
                int bb = job >> 3;
                int len = __ldg(tlens + bb);
                int tmin = (job & 7) * 64;
                if (tmin > len) continue;
                int t0 = tmin + w16 * 4;

                float lfv[4];
#pragma unroll
                for (int j = 0; j < 4; j++)
                    lfv[j] = __ldg(&g_lf[(size_t)((bb << 9) + t0 + j) * 32 + lane]);

                ull acc[4][8];
#pragma unroll
                for (int j = 0; j < 4; j++)
#pragma unroll
                    for (int i = 0; i < 8; i++) acc[j][i] = 0;

#pragma unroll 2
                for (int f = 0; f < 32; f++) {
                    ull d0 = dup2(__shfl_sync(0xffffffffu, lfv[0], f));
                    ull d1 = dup2(__shfl_sync(0xffffffffu, lfv[1], f));
                    ull d2 = dup2(__shfl_sync(0xffffffffu, lfv[2], f));
                    ull d3 = dup2(__shfl_sync(0xffffffffu, lfv[3], f));
                    const ull* lw = locwp + f * 256 + lane;
#pragma unroll
                    for (int i = 0; i < 8; i++) {
                        ull w2 = lw[32 * i];
                        fma2(acc[0][i], d0, w2);
                        fma2(acc[1][i], d1, w2);
                        fma2(acc[2][i], d2, w2);
                        fma2(acc[3][i], d3, w2);
                    }
                }
                const float* qb = g_q + (bb << 9);
#pragma unroll
                for (int j = 0; j < 4; j++) {
                    int t = t0 + j;
                    if (t > len) continue;
                    float p = 0.f;
                    const float* kp = g_keys + (size_t)((bb << 9) + t) * 512;
#pragma unroll
                    for (int i = 0; i < 8; i++) {
                        float2 av = unpk(acc[j][i]);
                        int a = lane + 32 * i;
                        float v1 = av.x + __ldg(qb + a)       + locb_s[a]       + __ldg(kp + a);
                        float v2 = av.y + __ldg(qb + a + 256) + locb_s[a + 256] + __ldg(kp + a + 256);
                        p = fmaf(ftanh(v1), sw_s[a], p);
                        p = fmaf(ftanh(v2), sw_s[a + 256], p);
                    }
#pragma unroll
                    for (int o = 16; o; o >>= 1) p += __shfl_xor_sync(0xffffffffu, p, o);
                    if (lane == 0) g_s[(bb << 9) + t] = p + sbv;
                }
            }
        }
        gsync(gen);

        // P4: softmax + attcum + context (blk<32)
        if (blk < NB) {
            int b = blk;
            int len = tlens[b];
            float* shw  = sc;
            float* ctmp = sc + 512;
            float* redm = sc + 2560;
            bool valid = (tid <= len);
            float sv = valid ? g_s[(b << 9) + tid] : -1e30f;

            float m = sv;
#pragma unroll
            for (int o = 16; o; o >>= 1) m = fmaxf(m, __shfl_xor_sync(0xffffffffu, m, o));
            if (lane == 0) redm[w16] = m;
            __syncthreads();
            if (tid == 0) {
                float mm = redm[0];
#pragma unroll
                for (int i = 1; i < 16; i++) mm = fmaxf(mm, redm[i]);
                redm[16] = mm;
            }
            __syncthreads();
            float mx = redm[16];
            float e = valid ? __expf(sv - mx) : 0.f;
            float ss = e;
#pragma unroll
            for (int o = 16; o; o >>= 1) ss += __shfl_xor_sync(0xffffffffu, ss, o);
            __syncthreads();
            if (lane == 0) redm[w16] = ss;
            __syncthreads();
            if (tid == 0) {
                float t = 0.f;
#pragma unroll
                for (int i = 0; i < 16; i++) t += redm[i];
                redm[17] = __fdividef(1.f, t);
            }
            __syncthreads();
            float w = e * redm[17];

            g_attw[(b << 9) + tid] = w;
            g_attcum[(b << 9) + tid] += w;
            out_attn[(size_t)(b * TM + step) * 512 + tid] = w;
            shw[tid] = w;
            __syncthreads();

            int tq = tid >> 7, a4 = (tid & 127) * 4;
            float4 c4 = make_float4(0.f, 0.f, 0.f, 0.f);
            for (int t = tq; t <= len; t += 4) {
                float wv = shw[t];
                float4 kv = *(const float4*)(g_keys + ((size_t)(b << 9) + t) * 512 + a4);
                c4.x = fmaf(wv, kv.x, c4.x);
                c4.y = fmaf(wv, kv.y, c4.y);
                c4.z = fmaf(wv, kv.z, c4.z);
                c4.w = fmaf(wv, kv.w, c4.w);
            }
            *(float4*)(ctmp + tq * 512 + a4) = c4;
            __syncthreads();
            float c = ctmp[tid] + ctmp[512 + tid] + ctmp[1024 + tid] + ctmp[1536 + tid];
            g_ctxT[tid * 32 + b] = c;
            g_ctxR[(b << 9) + tid] = c;
        }
        gsync(gen);

        // P5: output GRU (writes hoC + hoR)
        gru_phase(g_w2p, 1024, 1536, out_bi, out_bh,
                  haC, 512, g_ctxT, hoP, hoC, g_hoR, sc);
        gsync(gen);

        // P6: mel / gate / prenet (blk<32), coalesced staging from hoR/ctxR
        if (blk < NB) {
            int b = blk;
            float* xh   = sc;
            float* melS = sc + 1024;
            float* p1S  = sc + 1152;
            float* gred = sc + 1408;
            xh[tid]       = __ldg(&g_hoR[(b << 9) + tid]);
            xh[512 + tid] = __ldg(&g_ctxR[(b << 9) + tid]);
            __syncthreads();

#pragma unroll
            for (int r = 0; r < 8; r++) {
                int mm = w16 * 8 + r;
                const float4* dw = (const float4*)(g_decT + (size_t)mm * 1024) + lane;
                float acc = 0.f;
#pragma unroll
                for (int c = 0; c < 8; c++) {
                    float4 wv = __ldg(dw + c * 32);
                    float4 xv = *(const float4*)(xh + (c * 32 + lane) * 4);
                    acc = fmaf(wv.x, xv.x, fmaf(wv.y, xv.y, fmaf(wv.z, xv.z, fmaf(wv.w, xv.w, acc))));
                }
#pragma unroll
                for (int o = 16; o; o >>= 1) acc += __shfl_xor_sync(0xffffffffu, acc, o);
                if (lane == 0) melS[mm] = acc + __ldg(dec_b + mm);
            }
            {
                float gp = xh[tid] * __ldg(gate_w + tid) + xh[512 + tid] * __ldg(gate_w + 512 + tid);
#pragma unroll
                for (int o = 16; o; o >>= 1) gp += __shfl_xor_sync(0xffffffffu, gp, o);
                if (lane == 0) gred[w16] = gp;
            }
            __syncthreads();

            int mask = step > mlens[b];
            if (tid < 128)
                out_mel[(size_t)(b * TM + step) * 128 + tid] = mask ? 0.f : melS[tid];
            if (tid == 0) {
                float g = __ldg(gate_b);
#pragma unroll
                for (int i = 0; i < 16; i++) g += gred[i];
                out_gate[b * TM + step] = mask ? 1000.f : g;
                out_mask[b * TM + step] = mask ? 1.f : 0.f;
            }
            __syncthreads();

#pragma unroll
            for (int r = 0; r < 16; r++) {
                int p = w16 * 16 + r;
                float4 wv = __ldg((const float4*)(g_p1T + p * 128) + lane);
                float4 xv = *(const float4*)(melS + lane * 4);
                float acc = fmaf(wv.x, xv.x, fmaf(wv.y, xv.y, fmaf(wv.z, xv.z, wv.w * xv.w)));
#pragma unroll
                for (int o = 16; o; o >>= 1) acc += __shfl_xor_sync(0xffffffffu, acc, o);
                if (lane == 0) p1S[p] = fmaxf(acc, 0.f);
            }
            __syncthreads();

#pragma unroll
            for (int r = 0; r < 16; r++) {
                int p = w16 * 16 + r;
                const float4* w4 = (const float4*)(g_p2T + p * 256) + lane;
                float acc = 0.f;
#pragma unroll
                for (int c = 0; c < 2; c++) {
                    float4 wv = __ldg(w4 + c * 32);
                    float4 xv = *(const float4*)(p1S + (c * 32 + lane) * 4);
                    acc = fmaf(wv.x, xv.x, fmaf(wv.y, xv.y, fmaf(wv.z, xv.z, fmaf(wv.w, xv.w, acc))));
                }
#pragma unroll
                for (int o = 16; o; o >>= 1) acc += __shfl_xor_sync(0xffffffffu, acc, o);
                if (lane == 0) g_decinT[p * 32 + b] = fmaxf(acc, 0.f);
            }
        }
        gsync(gen);
    }
}

extern "C" void kernel_launch(void* const* d_in, const int* in_sizes, int n_in,
                              void* d_out, int out_size) {
    int off = n_in - 26;
    auto W = [&](int i) -> const float* {
        return (const float*)d_in[i >= 5 ? i + off : i];
    };
    const float* enc = (const float*)d_in[0];
    const int* tlens = (const int*)d_in[2];
    const int* mlens = (const int*)d_in[3];
    const float* pre_w1 = W(5), *pre_w2 = W(6);
    const float* attn_wi = W(7), *attn_wh = W(8), *attn_bi = W(9), *attn_bh = W(10);
    const float* q_w = W(11), *k_w = W(12);
    const float* score_w = W(13), *score_b = W(14);
    const float* loc_cw = W(15), *loc_w = W(16), *loc_b = W(17);
    const float* out_wi = W(18), *out_wh = W(19), *out_bi = W(20), *out_bh = W(21);
    const float* dec_w = W(22), *dec_b = W(23);
    const float* gate_w = W(24), *gate_b = W(25);

    float* out = (float*)d_out;
    float* out_mel  = out;
    float* out_gate = out + (size_t)NB * TM * 128;
    float* out_attn = out_gate + (size_t)NB * TM;
    float* out_mask = out_attn + (size_t)NB * TM * 512;

    static int configured = 0;
    if (!configured) {
        cudaFuncSetAttribute(decoder_kernel,
                             cudaFuncAttributeMaxDynamicSharedMemorySize, SM_BYTES);
        configured = 1;
    }

    decoder_kernel<<<NCTA, NTHR, SM_BYTES>>>(
        enc, tlens, mlens, pre_w1, pre_w2,
        attn_wi, attn_wh, attn_bi, attn_bh,
        q_w, k_w, score_w, score_b,
        loc_cw, loc_w, loc_b,
        out_wi, out_wh, out_bi, out_bh,
        dec_w, dec_b, gate_w, gate_b,
        out_mel, out_gate, out_attn, out_mask);
}

// round 11
// speedup vs baseline: 1.1772x; 1.0170x over previous
#include <cuda_runtime.h>
#include <math.h>

#define NB   32
#define TE   512
#define TM   400
#define NCTA 148
#define NTHR 512

typedef unsigned long long ull;

#define SM_LOCWP  0
#define SM_CW     16384
#define SM_LOCB   (16384+1984)
#define SM_SW     (16384+1984+512)
#define SM_SCR    (16384+1984+1024)
#define SM_FLOATS (16384+1984+1024+12800)
#define SM_BYTES  (SM_FLOATS*4)

__device__ float  g_keys[(size_t)NB * TE * 512];
__device__ float4 g_w1p[1280 * 512];
__device__ float4 g_w2p[1536 * 512];
__device__ float  g_qwT[512 * 512];
__device__ float  g_decT[128 * 1024];
__device__ float  g_p1T[256 * 128];
__device__ float  g_p2T[256 * 256];
__device__ float  g_haT[2][512 * NB];
__device__ float  g_hoT[2][512 * NB];
__device__ float  g_haR[NB * 512];
__device__ float  g_hoR[NB * 512];
__device__ float  g_ctxR[NB * 512];
__device__ float  g_ctxT[512 * NB];
__device__ float  g_decinT[256 * NB];
__device__ float  g_q[NB * 512];
__device__ float  g_attw[NB * TE];
__device__ float  g_attcum[NB * TE];
__device__ float  g_s[NB * TE];
__device__ float  g_lf[(size_t)NB * TE * 32];
__device__ int    g_jc[TM];
__device__ unsigned g_cnt = 0;
__device__ volatile unsigned g_gen = 0;

__device__ __forceinline__ ull dup2(float v) {
    ull r; asm("mov.b64 %0, {%1, %1};" : "=l"(r) : "f"(v)); return r;
}
__device__ __forceinline__ void fma2(ull &d, ull a, ull b) {
    asm("fma.rn.f32x2 %0, %1, %2, %3;" : "=l"(d) : "l"(a), "l"(b), "l"(d));
}
__device__ __forceinline__ float2 unpk(ull v) {
    float2 r; asm("mov.b64 {%0, %1}, %2;" : "=f"(r.x), "=f"(r.y) : "l"(v)); return r;
}
__device__ __forceinline__ ull pk2(float x, float y) {
    ull r; asm("mov.b64 %0, {%1, %2};" : "=l"(r) : "f"(x), "f"(y)); return r;
}
__device__ __forceinline__ float frcp(float v) {
    float r; asm("rcp.approx.f32 %0, %1;" : "=f"(r) : "f"(v)); return r;
}

__device__ __forceinline__ void gsync(unsigned &gen) {
    __syncthreads();
    if (threadIdx.x == 0) {
        __threadfence();
        if (atomicAdd(&g_cnt, 1u) == NCTA - 1) {
            g_cnt = 0;
            __threadfence();
            g_gen = gen + 1;
        } else {
            while (g_gen == gen) { __nanosleep(32); }
        }
        __threadfence();
    }
    __syncthreads();
    gen++;
}

__device__ __forceinline__ float fsig(float v) {
    return __fdividef(1.f, 1.f + __expf(-v));
}
__device__ __forceinline__ float ftanh(float v) {
    float e = __expf(2.f * v);
    return 1.f - __fdividef(2.f, e + 1.f);
}

// GRU: CTA(blk<128)=[4b x 32h]; warps = 2 b-pairs x 8 K-splits
__device__ __forceinline__ void gru_phase(
    const float4* __restrict__ wp, int L, int Kt,
    const float* __restrict__ bi, const float* __restrict__ bh,
    const float* __restrict__ x0, int l0,
    const float* __restrict__ x1,
    const float* __restrict__ hprev, float* __restrict__ hnew,
    float* __restrict__ hnewR, float* sc)
{
    int blk = blockIdx.x;
    if (blk >= 128) { __syncthreads(); __syncthreads(); return; }
    float* sx  = sc;
    float* red = sc + 6144;
    int tid = threadIdx.x, lane = tid & 31, w16 = tid >> 5;
    int b0 = (blk >> 4) * 4;
    int h  = (blk & 15) * 32 + lane;

    for (int k = w16; k < Kt; k += 16) {
        const float* src = (k < l0) ? (x0 + k * 32)
                         : (k < L)  ? (x1 + (k - l0) * 32)
                                    : (hprev + (k - L) * 32);
        float v = src[lane];
        int d = lane - b0;
        if ((unsigned)d < 4u) sx[k * 4 + d] = v;
    }
    __syncthreads();

    int bg = w16 >> 3, kq = w16 & 7;
    int kb = (kq * Kt) >> 3, ke = ((kq + 1) * Kt) >> 3;
    ull ai0 = 0, ai1 = 0, ai2 = 0, ah0 = 0, ah1 = 0, ah2 = 0;

    const float4* wph = wp + h;
    int s1e = ke < L ? ke : L;
#pragma unroll 4
    for (int k = kb; k < s1e; k++) {
        float4 wv = __ldg(wph + (size_t)k * 512);
        ull xp = *(const ull*)(sx + k * 4 + bg * 2);
        fma2(ai0, xp, dup2(wv.x));
        fma2(ai1, xp, dup2(wv.y));
        fma2(ai2, xp, dup2(wv.z));
    }
    int s2b = kb > L ? kb : L;
#pragma unroll 4
    for (int k = s2b; k < ke; k++) {
        float4 wv = __ldg(wph + (size_t)k * 512);
        ull xp = *(const ull*)(sx + k * 4 + bg * 2);
        fma2(ah0, xp, dup2(wv.x));
        fma2(ah1, xp, dup2(wv.y));
        fma2(ah2, xp, dup2(wv.z));
    }
    {
        float* r = red + tid * 13;
        float2 t;
        t = unpk(ai0); r[0] = t.x; r[6]  = t.y;
        t = unpk(ai1); r[1] = t.x; r[7]  = t.y;
        t = unpk(ai2); r[2] = t.x; r[8]  = t.y;
        t = unpk(ah0); r[3] = t.x; r[9]  = t.y;
        t = unpk(ah1); r[4] = t.x; r[10] = t.y;
        t = unpk(ah2); r[5] = t.x; r[11] = t.y;
    }
    __syncthreads();

    if (tid < 128) {
        int bj = tid >> 5;
        int b = b0 + bj;
        int hh = (blk & 15) * 32 + lane;
        int bgr = bj >> 1, jr = bj & 1;
        float gs[6] = {0.f, 0.f, 0.f, 0.f, 0.f, 0.f};
#pragma unroll
        for (int k2 = 0; k2 < 8; k2++) {
            const float* r = red + ((bgr * 8 + k2) * 32 + lane) * 13 + jr * 6;
#pragma unroll
            for (int g = 0; g < 6; g++) gs[g] += r[g];
        }
        float r = fsig(gs[0] + __ldg(bi + hh) + gs[3] + __ldg(bh + hh));
        float z = fsig(gs[1] + __ldg(bi + 512 + hh) + gs[4] + __ldg(bh + 512 + hh));
        float n = ftanh(gs[2] + __ldg(bi + 1024 + hh) + r * (gs[5] + __ldg(bh + 1024 + hh)));
        float hp = hprev[hh * 32 + b];
        float val = (1.f - z) * n + z * hp;
        hnew[hh * 32 + b] = val;
        hnewR[b * 512 + hh] = val;
    }
    __syncthreads();
}

__global__ void __launch_bounds__(NTHR, 1) decoder_kernel(
    const float* __restrict__ enc, const int* __restrict__ tlens, const int* __restrict__ mlens,
    const float* __restrict__ pre_w1, const float* __restrict__ pre_w2,
    const float* __restrict__ attn_wi, const float* __restrict__ attn_wh,
    const float* __restrict__ attn_bi, const float* __restrict__ attn_bh,
    const float* __restrict__ q_w, const float* __restrict__ k_w,
    const float* __restrict__ score_w, const float* __restrict__ score_b,
    const float* __restrict__ loc_cw, const float* __restrict__ loc_w, const float* __restrict__ loc_b,
    const float* __restrict__ out_wi, const float* __restrict__ out_wh,
    const float* __restrict__ out_bi, const float* __restrict__ out_bh,
    const float* __restrict__ dec_w, const float* __restrict__ dec_b,
    const float* __restrict__ gate_w, const float* __restrict__ gate_b,
    float* __restrict__ out_mel, float* __restrict__ out_gate,
    float* __restrict__ out_attn, float* __restrict__ out_mask)
{
    extern __shared__ float sm[];
    ull*   locwp  = (ull*)(sm + SM_LOCWP);
    float* cw_s   = sm + SM_CW;
    float* locb_s = sm + SM_LOCB;
    float* sw_s   = sm + SM_SW;
    float* sc     = sm + SM_SCR;
    __shared__ int sjob;

    int blk = blockIdx.x, tid = threadIdx.x, lane = tid & 31, w16 = tid >> 5;
    int gid = blk * NTHR + tid, gstride = NCTA * NTHR;
    unsigned gen = g_gen;

    for (int v = tid; v < 8192; v += NTHR) {
        int f = v >> 8, ap = v & 255;
        locwp[v] = pk2(loc_w[f * 512 + ap], loc_w[f * 512 + ap + 256]);
    }
    for (int v = tid; v < 1984; v += NTHR) cw_s[v] = loc_cw[v];
    for (int v = tid; v < 512; v += NTHR) { locb_s[v] = loc_b[v]; sw_s[v] = score_w[v]; }

    for (int v = gid; v < 512 * NB; v += gstride) {
        g_haT[0][v] = 0.f; g_hoT[0][v] = 0.f; g_ctxT[v] = 0.f; g_haR[v] = 0.f;
    }
    for (int v = gid; v < 256 * NB; v += gstride) g_decinT[v] = 0.f;
    for (int v = gid; v < NB * TE; v += gstride) { g_attw[v] = 0.f; g_attcum[v] = 0.f; }
    for (size_t v = gid; v < (size_t)NB * TE * 32; v += gstride) g_lf[v] = 0.f;
    for (int v = gid; v < TM; v += gstride) g_jc[v] = 0;

    for (int idx = gid; idx < 1280 * 512; idx += gstride) {
        int k = idx >> 9, h = idx & 511;
        const float* src = (k < 768) ? (attn_wi + (size_t)k * 1536)
                                     : (attn_wh + (size_t)(k - 768) * 1536);
        g_w1p[idx] = make_float4(src[h], src[h + 512], src[h + 1024], 0.f);
    }
    for (int idx = gid; idx < 1536 * 512; idx += gstride) {
        int k = idx >> 9, h = idx & 511;
        const float* src = (k < 1024) ? (out_wi + (size_t)k * 1536)
                                      : (out_wh + (size_t)(k - 1024) * 1536);
        g_w2p[idx] = make_float4(src[h], src[h + 512], src[h + 1024], 0.f);
    }
    for (int idx = gid; idx < 512 * 512; idx += gstride) {
        int a = idx >> 9, k = idx & 511;
        g_qwT[idx] = q_w[(size_t)k * 512 + a];
    }
    for (int idx = gid; idx < 128 * 1024; idx += gstride) {
        int m = idx >> 10, k = idx & 1023;
        g_decT[idx] = dec_w[(size_t)k * 128 + m];
    }
    for (int idx = gid; idx < 256 * 128; idx += gstride) {
        int p = idx >> 7, m = idx & 127;
        g_p1T[idx] = pre_w1[m * 256 + p];
    }
    for (int idx = gid; idx < 256 * 256; idx += gstride) {
        int p = idx >> 8, k = idx & 255;
        g_p2T[idx] = pre_w2[k * 256 + p];
    }

    // keys_p = enc @ k_w
    {
        int a = w16 * 32 + lane;
        for (int job = blk; job < 512; job += NCTA) {
            int b = job >> 4, tc2 = (job & 15) * 32;
            float a0[32];
#pragma unroll
            for (int t = 0; t < 32; t++) a0[t] = 0.f;
            for (int k0 = 0; k0 < 1024; k0 += 32) {
                __syncthreads();
                for (int v = tid; v < 1024; v += NTHR)
                    sc[v] = enc[(size_t)(b * TE + tc2 + (v >> 5)) * 1024 + k0 + (v & 31)];
                __syncthreads();
#pragma unroll
                for (int k4 = 0; k4 < 8; k4++) {
                    const float* kwp = k_w + (size_t)(k0 + k4 * 4) * 512 + a;
                    float w0 = __ldg(kwp), w1 = __ldg(kwp + 512), w2 = __ldg(kwp + 1024), w3 = __ldg(kwp + 1536);
#pragma unroll
                    for (int t = 0; t < 32; t++) {
                        float4 e = *(const float4*)(sc + t * 32 + k4 * 4);
                        a0[t] = fmaf(e.x, w0, fmaf(e.y, w1, fmaf(e.z, w2, fmaf(e.w, w3, a0[t]))));
                    }
                }
            }
#pragma unroll
            for (int t = 0; t < 32; t++)
                g_keys[(size_t)(b * TE + tc2 + t) * 512 + a] = a0[t];
        }
    }
    gsync(gen);

    for (int step = 0; step < TM; step++) {
        int prev = step & 1, cur = prev ^ 1;
        float* haP = g_haT[prev]; float* haC = g_haT[cur];
        float* hoP = g_hoT[prev]; float* hoC = g_hoT[cur];

        // P1: attention GRU (writes haC + haR)
        gru_phase(g_w1p, 768, 1280, attn_bi, attn_bh,
                  g_decinT, 256, g_ctxT, haP, haC, g_haR, sc);
        gsync(gen);

        // P2: q projection on all CTAs (512 jobs, reads haR coalesced)
        for (int j = blk; j < 512; j += NCTA) {
            int b = j >> 4;
            const float* xr = g_haR + (b << 9);
#pragma unroll
            for (int rr = 0; rr < 2; rr++) {
                int a = (j & 15) * 32 + w16 * 2 + rr;
                const float4* qw4 = (const float4*)(g_qwT + (size_t)a * 512) + lane;
                const float4* xv4 = (const float4*)xr + lane;
                float acc = 0.f;
#pragma unroll
                for (int c = 0; c < 4; c++) {
                    float4 wv = __ldg(qw4 + c * 32);
                    float4 xv = __ldg(xv4 + c * 32);
                    acc = fmaf(wv.x, xv.x, fmaf(wv.y, xv.y, fmaf(wv.z, xv.z, fmaf(wv.w, xv.w, acc))));
                }
#pragma unroll
                for (int o = 16; o; o >>= 1) acc += __shfl_xor_sync(0xffffffffu, acc, o);
                if (lane == 0) g_q[(b << 9) + a] = acc;
            }
        }
        gsync(gen);

        // P3: score via work queue (256 jobs of 64t), quad-batched tanh
        {
            float* sql = sc;   // 512: q + locb staged per job
            float sbv = __ldg(score_b);
            for (;;) {
                __syncthreads();
                if (tid == 0) sjob = atomicAdd(&g_jc[step], 1);
                __syncthreads();
                int job = sjob;
                if (job >= 256) break;
                int bb = job >> 3;
                int len = __ldg(tlens + bb);
                int tmin = (job & 7) * 64;
                if (tmin > len) continue;
                int t0 = tmin + w16 * 4;

                sql[tid] = __ldg(&g_q[(bb << 9) + tid]) + locb_s[tid];

                float lfv[4];
#pragma unroll
                for (int j = 0; j < 4; j++)
                    lfv[j] = __ldg(&g_lf[(size_t)((bb << 9) + t0 + j) * 32 + lane]);

                ull acc[4][8];
#pragma unroll
                for (int j = 0; j < 4; j++)
#pragma unroll
                    for (int i = 0; i < 8; i++) acc[j][i] = 0;

#pragma unroll 2
                for (int f = 0; f < 32; f++) {
                    ull d0 = dup2(__shfl_sync(0xffffffffu, lfv[0], f));
                    ull d1 = dup2(__shfl_sync(0xffffffffu, lfv[1], f));
                    ull d2 = dup2(__shfl_sync(0xffffffffu, lfv[2], f));
                    ull d3 = dup2(__shfl_sync(0xffffffffu, lfv[3], f));
                    const ull* lw = locwp + f * 256 + lane;
#pragma unroll
                    for (int i = 0; i < 8; i++) {
                        ull w2 = lw[32 * i];
                        fma2(acc[0][i], d0, w2);
                        fma2(acc[1][i], d1, w2);
                        fma2(acc[2][i], d2, w2);
                        fma2(acc[3][i], d3, w2);
                    }
                }
                __syncthreads();   // sql visible to all warps
#pragma unroll
                for (int j = 0; j < 4; j++) {
                    int t = t0 + j;
                    if (t > len) continue;
                    float p = 0.f;
                    const float* kp = g_keys + (size_t)((bb << 9) + t) * 512;
#pragma unroll
                    for (int i = 0; i < 8; i += 2) {
                        float2 av0 = unpk(acc[j][i]);
                        float2 av1 = unpk(acc[j][i + 1]);
                        int a0 = lane + 32 * i, a1 = a0 + 32;
                        float v0 = av0.x + sql[a0]       + __ldg(kp + a0);
                        float v1 = av0.y + sql[a0 + 256] + __ldg(kp + a0 + 256);
                        float v2 = av1.x + sql[a1]       + __ldg(kp + a1);
                        float v3 = av1.y + sql[a1 + 256] + __ldg(kp + a1 + 256);
                        v0 = fminf(fmaxf(v0, -9.f), 9.f);
                        v1 = fminf(fmaxf(v1, -9.f), 9.f);
                        v2 = fminf(fmaxf(v2, -9.f), 9.f);
                        v3 = fminf(fmaxf(v3, -9.f), 9.f);
                        float p0 = __expf(2.f * v0) + 1.f;
                        float p1 = __expf(2.f * v1) + 1.f;
                        float p2 = __expf(2.f * v2) + 1.f;
                        float p3 = __expf(2.f * v3) + 1.f;
                        float c1 = p0 * p1, c2 = c1 * p2, c3 = c2 * p3;
                        float rr = frcp(c3);
                        float i3 = c2 * rr; rr *= p3;
                        float i2 = c1 * rr; rr *= p2;
                        float i1 = p0 * rr;
                        float i0 = rr * p1;
                        p = fmaf(fmaf(-2.f, i0, 1.f), sw_s[a0],       p);
                        p = fmaf(fmaf(-2.f, i1, 1.f), sw_s[a0 + 256], p);
                        p = fmaf(fmaf(-2.f, i2, 1.f), sw_s[a1],       p);
                        p = fmaf(fmaf(-2.f, i3, 1.f), sw_s[a1 + 256], p);
                    }
#pragma unroll
                    for (int o = 16; o; o >>= 1) p += __shfl_xor_sync(0xffffffffu, p, o);
                    if (lane == 0) g_s[(bb << 9) + t] = p + sbv;
                }
            }
        }
        gsync(gen);

        // P4: softmax + attcum + context (blk<32)
        if (blk < NB) {
            int b = blk;
            int len = tlens[b];
            float* shw  = sc;
            float* ctmp = sc + 512;
            float* redm = sc + 2560;
            bool valid = (tid <= len);
            float sv = valid ? g_s[(b << 9) + tid] : -1e30f;

            float m = sv;
#pragma unroll
            for (int o = 16; o; o >>= 1) m = fmaxf(m, __shfl_xor_sync(0xffffffffu, m, o));
            if (lane == 0) redm[w16] = m;
            __syncthreads();
            if (tid == 0) {
                float mm = redm[0];
#pragma unroll
                for (int i = 1; i < 16; i++) mm = fmaxf(mm, redm[i]);
                redm[16] = mm;
            }
            __syncthreads();
            float mx = redm[16];
            float e = valid ? __expf(sv - mx) : 0.f;
            float ss = e;
#pragma unroll
            for (int o = 16; o; o >>= 1) ss += __shfl_xor_sync(0xffffffffu, ss, o);
            __syncthreads();
            if (lane == 0) redm[w16] = ss;
            __syncthreads();
            if (tid == 0) {
                float t = 0.f;
#pragma unroll
                for (int i = 0; i < 16; i++) t += redm[i];
                redm[17] = __fdividef(1.f, t);
            }
            __syncthreads();
            float w = e * redm[17];

            g_attw[(b << 9) + tid] = w;
            g_attcum[(b << 9) + tid] += w;
            out_attn[(size_t)(b * TM + step) * 512 + tid] = w;
            shw[tid] = w;
            __syncthreads();

            int tq = tid >> 7, a4 = (tid & 127) * 4;
            float4 c4 = make_float4(0.f, 0.f, 0.f, 0.f);
            for (int t = tq; t <= len; t += 4) {
                float wv = shw[t];
                float4 kv = *(const float4*)(g_keys + ((size_t)(b << 9) + t) * 512 + a4);
                c4.x = fmaf(wv, kv.x, c4.x);
                c4.y = fmaf(wv, kv.y, c4.y);
                c4.z = fmaf(wv, kv.z, c4.z);
                c4.w = fmaf(wv, kv.w, c4.w);
            }
            *(float4*)(ctmp + tq * 512 + a4) = c4;
            __syncthreads();
            float c = ctmp[tid] + ctmp[512 + tid] + ctmp[1024 + tid] + ctmp[1536 + tid];
            g_ctxT[tid * 32 + b] = c;
            g_ctxR[(b << 9) + tid] = c;
        }
        gsync(gen);

        // P5: output GRU (writes hoC + hoR)
        gru_phase(g_w2p, 1024, 1536, out_bi, out_bh,
                  haC, 512, g_ctxT, hoP, hoC, g_hoR, sc);
        gsync(gen);

        // P6: mel/gate/prenet (blk<32) || location conv for next step (blk>=32)
        if (blk < NB) {
            int b = blk;
            float* xh   = sc;
            float* melS = sc + 1024;
            float* p1S  = sc + 1152;
            float* gred = sc + 1408;
            xh[tid]       = __ldg(&g_hoR[(b << 9) + tid]);
            xh[512 + tid] = __ldg(&g_ctxR[(b << 9) + tid]);
            __syncthreads();

#pragma unroll
            for (int r = 0; r < 8; r++) {
                int mm = w16 * 8 + r;
                const float4* dw = (const float4*)(g_decT + (size_t)mm * 1024) + lane;
                float acc = 0.f;
#pragma unroll
                for (int c = 0; c < 8; c++) {
                    float4 wv = __ldg(dw + c * 32);
                    float4 xv = *(const float4*)(xh + (c * 32 + lane) * 4);
                    acc = fmaf(wv.x, xv.x, fmaf(wv.y, xv.y, fmaf(wv.z, xv.z, fmaf(wv.w, xv.w, acc))));
                }
#pragma unroll
                for (int o = 16; o; o >>= 1) acc += __shfl_xor_sync(0xffffffffu, acc, o);
                if (lane == 0) melS[mm] = acc + __ldg(dec_b + mm);
            }
            {
                float gp = xh[tid] * __ldg(gate_w + tid) + xh[512 + tid] * __ldg(gate_w + 512 + tid);
#pragma unroll
                for (int o = 16; o; o >>= 1) gp += __shfl_xor_sync(0xffffffffu, gp, o);
                if (lane == 0) gred[w16] = gp;
            }
            __syncthreads();

            int mask = step > mlens[b];
            if (tid < 128)
                out_mel[(size_t)(b * TM + step) * 128 + tid] = mask ? 0.f : melS[tid];
            if (tid == 0) {
                float g = __ldg(gate_b);
#pragma unroll
                for (int i = 0; i < 16; i++) g += gred[i];
                out_gate[b * TM + step] = mask ? 1000.f : g;
                out_mask[b * TM + step] = mask ? 1.f : 0.f;
            }
            __syncthreads();

#pragma unroll
            for (int r = 0; r < 16; r++) {
                int p = w16 * 16 + r;
                float4 wv = __ldg((const float4*)(g_p1T + p * 128) + lane);
                float4 xv = *(const float4*)(melS + lane * 4);
                float acc = fmaf(wv.x, xv.x, fmaf(wv.y, xv.y, fmaf(wv.z, xv.z, wv.w * xv.w)));
#pragma unroll
                for (int o = 16; o; o >>= 1) acc += __shfl_xor_sync(0xffffffffu, acc, o);
                if (lane == 0) p1S[p] = fmaxf(acc, 0.f);
            }
            __syncthreads();

#pragma unroll
            for (int r = 0; r < 16; r++) {
                int p = w16 * 16 + r;
                const float4* w4 = (const float4*)(g_p2T + p * 256) + lane;
                float acc = 0.f;
#pragma unroll
                for (int c = 0; c < 2; c++) {
                    float4 wv = __ldg(w4 + c * 32);
                    float4 xv = *(const float4*)(p1S + (c * 32 + lane) * 4);
                    acc = fmaf(wv.x, xv.x, fmaf(wv.y, xv.y, fmaf(wv.z, xv.z, fmaf(wv.w, xv.w, acc))));
                }
#pragma unroll
                for (int o = 16; o; o >>= 1) acc += __shfl_xor_sync(0xffffffffu, acc, o);
                if (lane == 0) g_decinT[p * 32 + b] = fmaxf(acc, 0.f);
            }
        } else if (step + 1 < TM) {
            // conv for NEXT step on otherwise-idle CTAs (116 CTAs, 128 jobs)
            for (int job = blk - NB; job < 128; job += NCTA - NB) {
                int b = job >> 2, tc2 = (job & 3) * 128;
                int len = tlens[b];
                if (tc2 <= len) {
                    float* sa  = sc;
                    float* sb2 = sc + 160;
                    for (int i = tid; i < 158; i += NTHR) {
                        int tt = tc2 + i - 15;
                        bool ok = (unsigned)tt < 512u;
                        sa[i]  = ok ? g_attw[b * 512 + tt]   : 0.f;
                        sb2[i] = ok ? g_attcum[b * 512 + tt] : 0.f;
                    }
                    __syncthreads();
                    int tb = w16 * 8;
                    float acc[8];
#pragma unroll
                    for (int j = 0; j < 8; j++) acc[j] = 0.f;
#pragma unroll 4
                    for (int kk = 0; kk < 31; kk++) {
                        float w0 = cw_s[lane * 62 + kk];
                        float w1 = cw_s[lane * 62 + 31 + kk];
#pragma unroll
                        for (int j = 0; j < 8; j++)
                            acc[j] = fmaf(sa[tb + kk + j], w0, fmaf(sb2[tb + kk + j], w1, acc[j]));
                    }
#pragma unroll
                    for (int j = 0; j < 8; j++)
                        g_lf[(size_t)(b * 512 + tc2 + tb + j) * 32 + lane] = acc[j];
                }
                __syncthreads();
            }
        }
        gsync(gen);
    }
}

extern "C" void kernel_launch(void* const* d_in, const int* in_sizes, int n_in,
                              void* d_out, int out_size) {
    int off = n_in - 26;
    auto W = [&](int i) -> const float* {
        return (const float*)d_in[i >= 5 ? i + off : i];
    };
    const float* enc = (const float*)d_in[0];
    const int* tlens = (const int*)d_in[2];
    const int* mlens = (const int*)d_in[3];
    const float* pre_w1 = W(5), *pre_w2 = W(6);
    const float* attn_wi = W(7), *attn_wh = W(8), *attn_bi = W(9), *attn_bh = W(10);
    const float* q_w = W(11), *k_w = W(12);
    const float* score_w = W(13), *score_b = W(14);
    const float* loc_cw = W(15), *loc_w = W(16), *loc_b = W(17);
    const float* out_wi = W(18), *out_wh = W(19), *out_bi = W(20), *out_bh = W(21);
    const float* dec_w = W(22), *dec_b = W(23);
    const float* gate_w = W(24), *gate_b = W(25);

    float* out = (float*)d_out;
    float* out_mel  = out;
    float* out_gate = out + (size_t)NB * TM * 128;
    float* out_attn = out_gate + (size_t)NB * TM;
    float* out_mask = out_attn + (size_t)NB * TM * 512;

    static int configured = 0;
    if (!configured) {
        cudaFuncSetAttribute(decoder_kernel,
                             cudaFuncAttributeMaxDynamicSharedMemorySize, SM_BYTES);
        configured = 1;
    }

    decoder_kernel<<<NCTA, NTHR, SM_BYTES>>>(
        enc, tlens, mlens, pre_w1, pre_w2,
        attn_wi, attn_wh, attn_bi, attn_bh,
        q_w, k_w, score_w, score_b,
        loc_cw, loc_w, loc_b,
        out_wi, out_wh, out_bi, out_bh,
        dec_w, dec_b, gate_w, gate_b,
        out_mel, out_gate, out_attn, out_mask);
}

// round 12
// speedup vs baseline: 1.9841x; 1.6854x over previous
#include <cuda_runtime.h>
#include <math.h>

#define NB   32
#define TE   512
#define TM   400
#define NCTA 148
#define NTHR 512

typedef unsigned long long ull;

#define SM_LOCWP  0
#define SM_CW     16384
#define SM_LOCB   (16384+1984)
#define SM_SW     (16384+1984+512)
#define SM_SCR    (16384+1984+1024)
#define SM_FLOATS (16384+1984+1024+12800)
#define SM_BYTES  (SM_FLOATS*4)

__device__ float  g_keys[(size_t)NB * TE * 512];
__device__ float4 g_w1p[1280 * 512];
__device__ float4 g_w2p[1536 * 512];
__device__ float  g_qwT[512 * 512];
__device__ float  g_decT[128 * 1024];
__device__ float  g_p1T[256 * 128];
__device__ float  g_p2T[256 * 256];
__device__ float  g_haT[2][512 * NB];
__device__ float  g_hoT[2][512 * NB];
__device__ float  g_haR[NB * 512];
__device__ float  g_hoR[NB * 512];
__device__ float  g_ctxR[NB * 512];
__device__ float  g_ctxT[512 * NB];
__device__ float  g_decinT[256 * NB];
__device__ float  g_q[NB * 512];
__device__ float  g_attw[NB * TE];
__device__ float  g_attcum[NB * TE];
__device__ float  g_s[NB * TE];
__device__ float  g_lf[(size_t)NB * TE * 32];
__device__ int    g_jc[TM];
__device__ unsigned g_cnt = 0;
__device__ volatile unsigned g_gen = 0;

__device__ __forceinline__ ull dup2(float v) {
    ull r; asm("mov.b64 %0, {%1, %1};" : "=l"(r) : "f"(v)); return r;
}
__device__ __forceinline__ void fma2(ull &d, ull a, ull b) {
    asm("fma.rn.f32x2 %0, %1, %2, %3;" : "=l"(d) : "l"(a), "l"(b), "l"(d));
}
__device__ __forceinline__ float2 unpk(ull v) {
    float2 r; asm("mov.b64 {%0, %1}, %2;" : "=f"(r.x), "=f"(r.y) : "l"(v)); return r;
}
__device__ __forceinline__ ull pk2(float x, float y) {
    ull r; asm("mov.b64 %0, {%1, %2};" : "=l"(r) : "f"(x), "f"(y)); return r;
}
__device__ __forceinline__ float frcp(float v) {
    float r; asm("rcp.approx.f32 %0, %1;" : "=f"(r) : "f"(v)); return r;
}

__device__ __forceinline__ void gsync(unsigned &gen) {
    __syncthreads();
    if (threadIdx.x == 0) {
        __threadfence();
        if (atomicAdd(&g_cnt, 1u) == NCTA - 1) {
            g_cnt = 0;
            __threadfence();
            g_gen = gen + 1;
        } else {
            while (g_gen == gen) { __nanosleep(32); }
        }
        __threadfence();
    }
    __syncthreads();
    gen++;
}

__device__ __forceinline__ float fsig(float v) {
    return __fdividef(1.f, 1.f + __expf(-v));
}
__device__ __forceinline__ float ftanh(float v) {
    float e = __expf(2.f * v);
    return 1.f - __fdividef(2.f, e + 1.f);
}

// GRU: CTA(blk<128) = 8 b-groups(4b) x 16 h-chunks(32h).
// 16 warps = 16 pure K-splits; each warp computes all 4 b (2 ull) x 32 h (lane).
__device__ __forceinline__ void gru_phase(
    const float4* __restrict__ wp, int L, int Kt,
    const float* __restrict__ bi, const float* __restrict__ bh,
    const float* __restrict__ x0, int l0,
    const float* __restrict__ x1,
    const float* __restrict__ hprev, float* __restrict__ hnew,
    float* __restrict__ hnewR, float* sc)
{
    int blk = blockIdx.x;
    if (blk >= 128) { __syncthreads(); __syncthreads(); return; }
    float* sx  = sc;          // [Kt][4] <= 6144 floats
    float* red = sc;          // reused after main loop: 512*24 = 12288
    int tid = threadIdx.x, lane = tid & 31, w16 = tid >> 5;
    int b0 = (blk >> 4) * 4;
    int hbase = (blk & 15) * 32;
    int h = hbase + lane;

    // stage x tile [k][4b], thread-per-element
    for (int v = tid; v < Kt * 4; v += NTHR) {
        int k = v >> 2, d = v & 3;
        const float* src = (k < l0) ? (x0 + k * 32)
                         : (k < L)  ? (x1 + (k - l0) * 32)
                                    : (hprev + (k - L) * 32);
        sx[v] = src[b0 + d];
    }
    __syncthreads();

    int KL = Kt >> 4;
    int kb = w16 * KL, ke = kb + KL;
    ull ar0 = 0, ar1 = 0, az0 = 0, az1 = 0, an0 = 0, an1 = 0;   // input gates
    ull br0 = 0, br1 = 0, bz0 = 0, bz1 = 0, bn0 = 0, bn1 = 0;   // hidden gates

    const float4* wrow = wp + h;
    int e1 = ke < L ? ke : L;
#pragma unroll 8
    for (int k = kb; k < e1; k++) {
        float4 wv = __ldg(wrow + (size_t)k * 512);
        ull x01 = *(const ull*)(sx + k * 4);
        ull x23 = *(const ull*)(sx + k * 4 + 2);
        ull dr = dup2(wv.x), dz = dup2(wv.y), dn = dup2(wv.z);
        fma2(ar0, x01, dr); fma2(ar1, x23, dr);
        fma2(az0, x01, dz); fma2(az1, x23, dz);
        fma2(an0, x01, dn); fma2(an1, x23, dn);
    }
    int s2 = kb > L ? kb : L;
#pragma unroll 8
    for (int k = s2; k < ke; k++) {
        float4 wv = __ldg(wrow + (size_t)k * 512);
        ull x01 = *(const ull*)(sx + k * 4);
        ull x23 = *(const ull*)(sx + k * 4 + 2);
        ull dr = dup2(wv.x), dz = dup2(wv.y), dn = dup2(wv.z);
        fma2(br0, x01, dr); fma2(br1, x23, dr);
        fma2(bz0, x01, dz); fma2(bz1, x23, dz);
        fma2(bn0, x01, dn); fma2(bn1, x23, dn);
    }
    __syncthreads();   // sx reads complete; reuse as reduction buffer
    {
        float* r = red + tid * 24;   // [cat(6)][b(4)]
        float2 t;
        t = unpk(ar0); r[0]  = t.x; r[1]  = t.y;
        t = unpk(ar1); r[2]  = t.x; r[3]  = t.y;
        t = unpk(az0); r[4]  = t.x; r[5]  = t.y;
        t = unpk(az1); r[6]  = t.x; r[7]  = t.y;
        t = unpk(an0); r[8]  = t.x; r[9]  = t.y;
        t = unpk(an1); r[10] = t.x; r[11] = t.y;
        t = unpk(br0); r[12] = t.x; r[13] = t.y;
        t = unpk(br1); r[14] = t.x; r[15] = t.y;
        t = unpk(bz0); r[16] = t.x; r[17] = t.y;
        t = unpk(bz1); r[18] = t.x; r[19] = t.y;
        t = unpk(bn0); r[20] = t.x; r[21] = t.y;
        t = unpk(bn1); r[22] = t.x; r[23] = t.y;
    }
    __syncthreads();

    if (tid < 128) {
        int bl = tid >> 5, hl = tid & 31;
        int hh = hbase + hl, b = b0 + bl;
        float g0 = 0.f, g1 = 0.f, g2 = 0.f, g3 = 0.f, g4 = 0.f, g5 = 0.f;
#pragma unroll
        for (int w = 0; w < 16; w++) {
            const float* r = red + (w * 32 + hl) * 24 + bl;
            g0 += r[0]; g1 += r[4]; g2 += r[8]; g3 += r[12]; g4 += r[16]; g5 += r[20];
        }
        float r = fsig(g0 + __ldg(bi + hh) + g3 + __ldg(bh + hh));
        float z = fsig(g1 + __ldg(bi + 512 + hh) + g4 + __ldg(bh + 512 + hh));
        float n = ftanh(g2 + __ldg(bi + 1024 + hh) + r * (g5 + __ldg(bh + 1024 + hh)));
        float hp = hprev[hh * 32 + b];
        float val = (1.f - z) * n + z * hp;
        hnew[hh * 32 + b] = val;
        hnewR[b * 512 + hh] = val;
    }
    __syncthreads();
}

__global__ void __launch_bounds__(NTHR, 1) decoder_kernel(
    const float* __restrict__ enc, const int* __restrict__ tlens, const int* __restrict__ mlens,
    const float* __restrict__ pre_w1, const float* __restrict__ pre_w2,
    const float* __restrict__ attn_wi, const float* __restrict__ attn_wh,
    const float* __restrict__ attn_bi, const float* __restrict__ attn_bh,
    const float* __restrict__ q_w, const float* __restrict__ k_w,
    const float* __restrict__ score_w, const float* __restrict__ score_b,
    const float* __restrict__ loc_cw, const float* __restrict__ loc_w, const float* __restrict__ loc_b,
    const float* __restrict__ out_wi, const float* __restrict__ out_wh,
    const float* __restrict__ out_bi, const float* __restrict__ out_bh,
    const float* __restrict__ dec_w, const float* __restrict__ dec_b,
    const float* __restrict__ gate_w, const float* __restrict__ gate_b,
    float* __restrict__ out_mel, float* __restrict__ out_gate,
    float* __restrict__ out_attn, float* __restrict__ out_mask)
{
    extern __shared__ float sm[];
    ull*   locwp  = (ull*)(sm + SM_LOCWP);
    float* cw_s   = sm + SM_CW;
    float* locb_s = sm + SM_LOCB;
    float* sw_s   = sm + SM_SW;
    float* sc     = sm + SM_SCR;
    __shared__ int sjob;

    int blk = blockIdx.x, tid = threadIdx.x, lane = tid & 31, w16 = tid >> 5;
    int gid = blk * NTHR + tid, gstride = NCTA * NTHR;
    unsigned gen = g_gen;

    for (int v = tid; v < 8192; v += NTHR) {
        int f = v >> 8, ap = v & 255;
        locwp[v] = pk2(loc_w[f * 512 + ap], loc_w[f * 512 + ap + 256]);
    }
    for (int v = tid; v < 1984; v += NTHR) cw_s[v] = loc_cw[v];
    for (int v = tid; v < 512; v += NTHR) { locb_s[v] = loc_b[v]; sw_s[v] = score_w[v]; }

    for (int v = gid; v < 512 * NB; v += gstride) {
        g_haT[0][v] = 0.f; g_hoT[0][v] = 0.f; g_ctxT[v] = 0.f; g_haR[v] = 0.f;
    }
    for (int v = gid; v < 256 * NB; v += gstride) g_decinT[v] = 0.f;
    for (int v = gid; v < NB * TE; v += gstride) { g_attw[v] = 0.f; g_attcum[v] = 0.f; }
    for (size_t v = gid; v < (size_t)NB * TE * 32; v += gstride) g_lf[v] = 0.f;
    for (int v = gid; v < TM; v += gstride) g_jc[v] = 0;

    for (int idx = gid; idx < 1280 * 512; idx += gstride) {
        int k = idx >> 9, h = idx & 511;
        const float* src = (k < 768) ? (attn_wi + (size_t)k * 1536)
                                     : (attn_wh + (size_t)(k - 768) * 1536);
        g_w1p[idx] = make_float4(src[h], src[h + 512], src[h + 1024], 0.f);
    }
    for (int idx = gid; idx < 1536 * 512; idx += gstride) {
        int k = idx >> 9, h = idx & 511;
        const float* src = (k < 1024) ? (out_wi + (size_t)k * 1536)
                                      : (out_wh + (size_t)(k - 1024) * 1536);
        g_w2p[idx] = make_float4(src[h], src[h + 512], src[h + 1024], 0.f);
    }
    for (int idx = gid; idx < 512 * 512; idx += gstride) {
        int a = idx >> 9, k = idx & 511;
        g_qwT[idx] = q_w[(size_t)k * 512 + a];
    }
    for (int idx = gid; idx < 128 * 1024; idx += gstride) {
        int m = idx >> 10, k = idx & 1023;
        g_decT[idx] = dec_w[(size_t)k * 128 + m];
    }
    for (int idx = gid; idx < 256 * 128; idx += gstride) {
        int p = idx >> 7, m = idx & 127;
        g_p1T[idx] = pre_w1[m * 256 + p];
    }
    for (int idx = gid; idx < 256 * 256; idx += gstride) {
        int p = idx >> 8, k = idx & 255;
        g_p2T[idx] = pre_w2[k * 256 + p];
    }

    // keys_p = enc @ k_w
    {
        int a = w16 * 32 + lane;
        for (int job = blk; job < 512; job += NCTA) {
            int b = job >> 4, tc2 = (job & 15) * 32;
            float a0[32];
#pragma unroll
            for (int t = 0; t < 32; t++) a0[t] = 0.f;
            for (int k0 = 0; k0 < 1024; k0 += 32) {
                __syncthreads();
                for (int v = tid; v < 1024; v += NTHR)
                    sc[v] = enc[(size_t)(b * TE + tc2 + (v >> 5)) * 1024 + k0 + (v & 31)];
                __syncthreads();
#pragma unroll
                for (int k4 = 0; k4 < 8; k4++) {
                    const float* kwp = k_w + (size_t)(k0 + k4 * 4) * 512 + a;
                    float w0 = __ldg(kwp), w1 = __ldg(kwp + 512), w2 = __ldg(kwp + 1024), w3 = __ldg(kwp + 1536);
#pragma unroll
                    for (int t = 0; t < 32; t++) {
                        float4 e = *(const float4*)(sc + t * 32 + k4 * 4);
                        a0[t] = fmaf(e.x, w0, fmaf(e.y, w1, fmaf(e.z, w2, fmaf(e.w, w3, a0[t]))));
                    }
                }
            }
#pragma unroll
            for (int t = 0; t < 32; t++)
                g_keys[(size_t)(b * TE + tc2 + t) * 512 + a] = a0[t];
        }
    }
    gsync(gen);

    for (int step = 0; step < TM; step++) {
        int prev = step & 1, cur = prev ^ 1;
        float* haP = g_haT[prev]; float* haC = g_haT[cur];
        float* hoP = g_hoT[prev]; float* hoC = g_hoT[cur];

        // P1: attention GRU
        gru_phase(g_w1p, 768, 1280, attn_bi, attn_bh,
                  g_decinT, 256, g_ctxT, haP, haC, g_haR, sc);
        gsync(gen);

        // P2: q projection on all CTAs (512 jobs, reads haR coalesced)
        for (int j = blk; j < 512; j += NCTA) {
            int b = j >> 4;
            const float* xr = g_haR + (b << 9);
#pragma unroll
            for (int rr = 0; rr < 2; rr++) {
                int a = (j & 15) * 32 + w16 * 2 + rr;
                const float4* qw4 = (const float4*)(g_qwT + (size_t)a * 512) + lane;
                const float4* xv4 = (const float4*)xr + lane;
                float acc = 0.f;
#pragma unroll
                for (int c = 0; c < 4; c++) {
                    float4 wv = __ldg(qw4 + c * 32);
                    float4 xv = __ldg(xv4 + c * 32);
                    acc = fmaf(wv.x, xv.x, fmaf(wv.y, xv.y, fmaf(wv.z, xv.z, fmaf(wv.w, xv.w, acc))));
                }
#pragma unroll
                for (int o = 16; o; o >>= 1) acc += __shfl_xor_sync(0xffffffffu, acc, o);
                if (lane == 0) g_q[(b << 9) + a] = acc;
            }
        }
        gsync(gen);

        // P3: score via work queue (256 jobs of 64t); lf staged as smem dup-pairs
        {
            ull*   sdl = (ull*)sc;        // [64t][32f] dup pairs = 2048 ull
            float* sql = sc + 4096;       // 512
            float sbv = __ldg(score_b);
            for (;;) {
                __syncthreads();
                if (tid == 0) sjob = atomicAdd(&g_jc[step], 1);
                __syncthreads();
                int job = sjob;
                if (job >= 256) break;
                int bb = job >> 3;
                int len = __ldg(tlens + bb);
                int tmin = (job & 7) * 64;
                if (tmin > len) continue;
                int t0 = tmin + w16 * 4;

                for (int e = tid; e < 2048; e += NTHR)
                    sdl[e] = dup2(__ldg(&g_lf[(size_t)((bb << 9) + tmin) * 32 + e]));
                sql[tid] = __ldg(&g_q[(bb << 9) + tid]) + locb_s[tid];
                __syncthreads();

                ull acc[4][8];
#pragma unroll
                for (int j = 0; j < 4; j++)
#pragma unroll
                    for (int i = 0; i < 8; i++) acc[j][i] = 0;

                const ull* lfd = sdl + (w16 * 4) * 32;
#pragma unroll 2
                for (int f = 0; f < 32; f++) {
                    ull d0 = lfd[f];
                    ull d1 = lfd[32 + f];
                    ull d2 = lfd[64 + f];
                    ull d3 = lfd[96 + f];
                    const ull* lw = locwp + f * 256 + lane;
#pragma unroll
                    for (int i = 0; i < 8; i++) {
                        ull w2 = lw[32 * i];
                        fma2(acc[0][i], d0, w2);
                        fma2(acc[1][i], d1, w2);
                        fma2(acc[2][i], d2, w2);
                        fma2(acc[3][i], d3, w2);
                    }
                }
#pragma unroll
                for (int j = 0; j < 4; j++) {
                    int t = t0 + j;
                    if (t > len) continue;
                    float p = 0.f;
                    const float* kp = g_keys + (size_t)((bb << 9) + t) * 512;
#pragma unroll
                    for (int i = 0; i < 8; i += 2) {
                        float2 av0 = unpk(acc[j][i]);
                        float2 av1 = unpk(acc[j][i + 1]);
                        int a0 = lane + 32 * i, a1 = a0 + 32;
                        float v0 = av0.x + sql[a0]       + __ldg(kp + a0);
                        float v1 = av0.y + sql[a0 + 256] + __ldg(kp + a0 + 256);
                        float v2 = av1.x + sql[a1]       + __ldg(kp + a1);
                        float v3 = av1.y + sql[a1 + 256] + __ldg(kp + a1 + 256);
                        v0 = fminf(fmaxf(v0, -9.f), 9.f);
                        v1 = fminf(fmaxf(v1, -9.f), 9.f);
                        v2 = fminf(fmaxf(v2, -9.f), 9.f);
                        v3 = fminf(fmaxf(v3, -9.f), 9.f);
                        float p0 = __expf(2.f * v0) + 1.f;
                        float p1 = __expf(2.f * v1) + 1.f;
                        float p2 = __expf(2.f * v2) + 1.f;
                        float p3 = __expf(2.f * v3) + 1.f;
                        float c1 = p0 * p1, c2 = c1 * p2, c3 = c2 * p3;
                        float rr = frcp(c3);
                        float i3 = c2 * rr; rr *= p3;
                        float i2 = c1 * rr; rr *= p2;
                        float i1 = p0 * rr;
                        float i0 = rr * p1;
                        p = fmaf(fmaf(-2.f, i0, 1.f), sw_s[a0],       p);
                        p = fmaf(fmaf(-2.f, i1, 1.f), sw_s[a0 + 256], p);
                        p = fmaf(fmaf(-2.f, i2, 1.f), sw_s[a1],       p);
                        p = fmaf(fmaf(-2.f, i3, 1.f), sw_s[a1 + 256], p);
                    }
#pragma unroll
                    for (int o = 16; o; o >>= 1) p += __shfl_xor_sync(0xffffffffu, p, o);
                    if (lane == 0) g_s[(bb << 9) + t] = p + sbv;
                }
            }
        }
        gsync(gen);

        // P4: softmax + attcum + context (blk<32)
        if (blk < NB) {
            int b = blk;
            int len = tlens[b];
            float* shw  = sc;
            float* ctmp = sc + 512;
            float* redm = sc + 2560;
            bool valid = (tid <= len);
            float sv = valid ? g_s[(b << 9) + tid] : -1e30f;

            float m = sv;
#pragma unroll
            for (int o = 16; o; o >>= 1) m = fmaxf(m, __shfl_xor_sync(0xffffffffu, m, o));
            if (lane == 0) redm[w16] = m;
            __syncthreads();
            if (tid == 0) {
                float mm = redm[0];
#pragma unroll
                for (int i = 1; i < 16; i++) mm = fmaxf(mm, redm[i]);
                redm[16] = mm;
            }
            __syncthreads();
            float mx = redm[16];
            float e = valid ? __expf(sv - mx) : 0.f;
            float ss = e;
#pragma unroll
            for (int o = 16; o; o >>= 1) ss += __shfl_xor_sync(0xffffffffu, ss, o);
            __syncthreads();
            if (lane == 0) redm[w16] = ss;
            __syncthreads();
            if (tid == 0) {
                float t = 0.f;
#pragma unroll
                for (int i = 0; i < 16; i++) t += redm[i];
                redm[17] = __fdividef(1.f, t);
            }
            __syncthreads();
            float w = e * redm[17];

            g_attw[(b << 9) + tid] = w;
            g_attcum[(b << 9) + tid] += w;
            out_attn[(size_t)(b * TM + step) * 512 + tid] = w;
            shw[tid] = w;
            __syncthreads();

            int tq = tid >> 7, a4 = (tid & 127) * 4;
            float4 c4 = make_float4(0.f, 0.f, 0.f, 0.f);
            for (int t = tq; t <= len; t += 4) {
                float wv = shw[t];
                float4 kv = *(const float4*)(g_keys + ((size_t)(b << 9) + t) * 512 + a4);
                c4.x = fmaf(wv, kv.x, c4.x);
                c4.y = fmaf(wv, kv.y, c4.y);
                c4.z = fmaf(wv, kv.z, c4.z);
                c4.w = fmaf(wv, kv.w, c4.w);
            }
            *(float4*)(ctmp + tq * 512 + a4) = c4;
            __syncthreads();
            float c = ctmp[tid] + ctmp[512 + tid] + ctmp[1024 + tid] + ctmp[1536 + tid];
            g_ctxT[tid * 32 + b] = c;
            g_ctxR[(b << 9) + tid] = c;
        }
        gsync(gen);

        // P5: output GRU
        gru_phase(g_w2p, 1024, 1536, out_bi, out_bh,
                  haC, 512, g_ctxT, hoP, hoC, g_hoR, sc);
        gsync(gen);

        // P6: mel/gate/prenet (blk<32) || location conv for next step (blk>=32)
        if (blk < NB) {
            int b = blk;
            float* xh   = sc;
            float* melS = sc + 1024;
            float* p1S  = sc + 1152;
            float* gred = sc + 1408;
            xh[tid]       = __ldg(&g_hoR[(b << 9) + tid]);
            xh[512 + tid] = __ldg(&g_ctxR[(b << 9) + tid]);
            __syncthreads();

#pragma unroll
            for (int r = 0; r < 8; r++) {
                int mm = w16 * 8 + r;
                const float4* dw = (const float4*)(g_decT + (size_t)mm * 1024) + lane;
                float acc = 0.f;
#pragma unroll
                for (int c = 0; c < 8; c++) {
                    float4 wv = __ldg(dw + c * 32);
                    float4 xv = *(const float4*)(xh + (c * 32 + lane) * 4);
                    acc = fmaf(wv.x, xv.x, fmaf(wv.y, xv.y, fmaf(wv.z, xv.z, fmaf(wv.w, xv.w, acc))));
                }
#pragma unroll
                for (int o = 16; o; o >>= 1) acc += __shfl_xor_sync(0xffffffffu, acc, o);
                if (lane == 0) melS[mm] = acc + __ldg(dec_b + mm);
            }
            {
                float gp = xh[tid] * __ldg(gate_w + tid) + xh[512 + tid] * __ldg(gate_w + 512 + tid);
#pragma unroll
                for (int o = 16; o; o >>= 1) gp += __shfl_xor_sync(0xffffffffu, gp, o);
                if (lane == 0) gred[w16] = gp;
            }
            __syncthreads();

            int mask = step > mlens[b];
            if (tid < 128)
                out_mel[(size_t)(b * TM + step) * 128 + tid] = mask ? 0.f : melS[tid];
            if (tid == 0) {
                float g = __ldg(gate_b);
#pragma unroll
                for (int i = 0; i < 16; i++) g += gred[i];
                out_gate[b * TM + step] = mask ? 1000.f : g;
                out_mask[b * TM + step] = mask ? 1.f : 0.f;
            }
            __syncthreads();

#pragma unroll
            for (int r = 0; r < 16; r++) {
                int p = w16 * 16 + r;
                float4 wv = __ldg((const float4*)(g_p1T + p * 128) + lane);
                float4 xv = *(const float4*)(melS + lane * 4);
                float acc = fmaf(wv.x, xv.x, fmaf(wv.y, xv.y, fmaf(wv.z, xv.z, wv.w * xv.w)));
#pragma unroll
                for (int o = 16; o; o >>= 1) acc += __shfl_xor_sync(0xffffffffu, acc, o);
                if (lane == 0) p1S[p] = fmaxf(acc, 0.f);
            }
            __syncthreads();

#pragma unroll
            for (int r = 0; r < 16; r++) {
                int p = w16 * 16 + r;
                const float4* w4 = (const float4*)(g_p2T + p * 256) + lane;
                float acc = 0.f;
#pragma unroll
                for (int c = 0; c < 2; c++) {
                    float4 wv = __ldg(w4 + c * 32);
                    float4 xv = *(const float4*)(p1S + (c * 32 + lane) * 4);
                    acc = fmaf(wv.x, xv.x, fmaf(wv.y, xv.y, fmaf(wv.z, xv.z, fmaf(wv.w, xv.w, acc))));
                }
#pragma unroll
                for (int o = 16; o; o >>= 1) acc += __shfl_xor_sync(0xffffffffu, acc, o);
                if (lane == 0) g_decinT[p * 32 + b] = fmaxf(acc, 0.f);
            }
        } else if (step + 1 < TM) {
            for (int job = blk - NB; job < 128; job += NCTA - NB) {
                int b = job >> 2, tc2 = (job & 3) * 128;
                int len = tlens[b];
                if (tc2 <= len) {
                    float* sa  = sc;
                    float* sb2 = sc + 160;
                    for (int i = tid; i < 158; i += NTHR) {
                        int tt = tc2 + i - 15;
                        bool ok = (unsigned)tt < 512u;
                        sa[i]  = ok ? g_attw[b * 512 + tt]   : 0.f;
                        sb2[i] = ok ? g_attcum[b * 512 + tt] : 0.f;
                    }
                    __syncthreads();
                    int tb = w16 * 8;
                    float acc[8];
#pragma unroll
                    for (int j = 0; j < 8; j++) acc[j] = 0.f;
#pragma unroll 4
                    for (int kk = 0; kk < 31; kk++) {
                        float w0 = cw_s[lane * 62 + kk];
                        float w1 = cw_s[lane * 62 + 31 + kk];
#pragma unroll
                        for (int j = 0; j < 8; j++)
                            acc[j] = fmaf(sa[tb + kk + j], w0, fmaf(sb2[tb + kk + j], w1, acc[j]));
                    }
#pragma unroll
                    for (int j = 0; j < 8; j++)
                        g_lf[(size_t)(b * 512 + tc2 + tb + j) * 32 + lane] = acc[j];
                }
                __syncthreads();
            }
        }
        gsync(gen);
    }
}

extern "C" void kernel_launch(void* const* d_in, const int* in_sizes, int n_in,
                              void* d_out, int out_size) {
    int off = n_in - 26;
    auto W = [&](int i) -> const float* {
        return (const float*)d_in[i >= 5 ? i + off : i];
    };
    const float* enc = (const float*)d_in[0];
    const int* tlens = (const int*)d_in[2];
    const int* mlens = (const int*)d_in[3];
    const float* pre_w1 = W(5), *pre_w2 = W(6);
    const float* attn_wi = W(7), *attn_wh = W(8), *attn_bi = W(9), *attn_bh = W(10);
    const float* q_w = W(11), *k_w = W(12);
    const float* score_w = W(13), *score_b = W(14);
    const float* loc_cw = W(15), *loc_w = W(16), *loc_b = W(17);
    const float* out_wi = W(18), *out_wh = W(19), *out_bi = W(20), *out_bh = W(21);
    const float* dec_w = W(22), *dec_b = W(23);
    const float* gate_w = W(24), *gate_b = W(25);

    float* out = (float*)d_out;
    float* out_mel  = out;
    float* out_gate = out + (size_t)NB * TM * 128;
    float* out_attn = out_gate + (size_t)NB * TM;
    float* out_mask = out_attn + (size_t)NB * TM * 512;

    static int configured = 0;
    if (!configured) {
        cudaFuncSetAttribute(decoder_kernel,
                             cudaFuncAttributeMaxDynamicSharedMemorySize, SM_BYTES);
        configured = 1;
    }

    decoder_kernel<<<NCTA, NTHR, SM_BYTES>>>(
        enc, tlens, mlens, pre_w1, pre_w2,
        attn_wi, attn_wh, attn_bi, attn_bh,
        q_w, k_w, score_w, score_b,
        loc_cw, loc_w, loc_b,
        out_wi, out_wh, out_bi, out_bh,
        dec_w, dec_b, gate_w, gate_b,
        out_mel, out_gate, out_attn, out_mask);
}